// round 11
// baseline (speedup 1.0000x reference)
#include <cuda_runtime.h>
#include <math.h>

#define BB 4
#define NN 4096
#define CC 64
#define ALPHA 0.2f
#define G  512          // scan chunks per batch
#define CH 8            // elements per chunk (NN = G*CH)
#define RUN 512         // sort run length
#define NRUN 8          // runs per batch
#define FULL 0xffffffffu

// ---------------- scratch (static device globals; no allocation) ----------------
__device__ __align__(16) float g_h[BB*NN*CC];        // h = feat @ W
__device__ __align__(16) float g_s1[BB*NN];
__device__ __align__(16) float g_s2[BB*NN];
__device__ float g_M2[BB];
__device__ __align__(16) float g_sval[BB*NN];        // sorted s2 (ascending) per batch
__device__ __align__(16) int   g_sidx[BB*NN];        // permutation
__device__ __align__(16) float g_E1[BB*NN];          // exp(sval - M2)
__device__ __align__(16) float g_E2[BB*NN];          // exp(alpha * sval)
__device__ __align__(16) unsigned long long g_runs[BB*NN]; // sorted runs (packed key|idx)
__device__ __align__(16) float g_SgeH[BB*(NN+1)*CC]; // suffix sums of E1*h
__device__ __align__(16) float g_SltH[BB*(NN+1)*CC]; // prefix sums of E2*h
__device__ __align__(16) float g_Sge1[BB*(NN+1)];
__device__ __align__(16) float g_Slt1[BB*(NN+1)];
// scan intermediates
__device__ __align__(16) float g_pl [BB*G*CC], g_pg [BB*G*CC];  // chunk partials
__device__ __align__(16) float g_ofL[BB*G*CC], g_ofG[BB*G*CC];  // chunk offsets
__device__ float g_ofLs[BB*G], g_ofGs[BB*G];                    // scalar offsets

// ---------------- K1: h = feat @ W, s1 = h.a1, s2 = h.a2 ----------------
__global__ __launch_bounds__(256) void k1_hsw(const float* __restrict__ feat,
                                              const float* __restrict__ W,
                                              const float* __restrict__ a)
{
    __shared__ float Ws[64*64];
    __shared__ float a1s[64], a2s[64];
    __shared__ float fs[4][64];
    __shared__ float p1[4][2], p2[4][2];

    int tid = threadIdx.x;                 // 256
    for (int i = tid; i < 64*64; i += 256) Ws[i] = W[i];
    if (tid < 64) { a1s[tid] = a[tid]; a2s[tid] = a[64 + tid]; }

    int rb = tid >> 6;                     // 0..3
    int c  = tid & 63;

    #pragma unroll
    for (int r = 0; r < 4; r++) {
        int row = blockIdx.x * 16 + r * 4 + rb;
        fs[rb][c] = feat[row*64 + c];
        __syncthreads();

        float acc0 = 0.f, acc1 = 0.f;
        #pragma unroll
        for (int k = 0; k < 64; k += 2) {
            acc0 = fmaf(fs[rb][k],   Ws[k*64 + c],     acc0);
            acc1 = fmaf(fs[rb][k+1], Ws[(k+1)*64 + c], acc1);
        }
        float acc = acc0 + acc1;
        g_h[row*64 + c] = acc;

        float v1 = acc * a1s[c];
        float v2 = acc * a2s[c];
        #pragma unroll
        for (int o = 16; o > 0; o >>= 1) {
            v1 += __shfl_down_sync(FULL, v1, o);
            v2 += __shfl_down_sync(FULL, v2, o);
        }
        if ((c & 31) == 0) { p1[rb][c>>5] = v1; p2[rb][c>>5] = v2; }
        __syncthreads();
        if (c == 0) {
            g_s1[row] = p1[rb][0] + p1[rb][1];
            g_s2[row] = p2[rb][0] + p2[rb][1];
        }
    }
}

// ---------------- bitonic helpers (packed u64 key|idx) ----------------
__device__ __forceinline__ void cswap2(unsigned long long r[4], int m0, int m1, bool asc)
{
    unsigned long long a = r[m0], b = r[m1];
    bool sw = asc ? (a > b) : (a < b);
    if (sw) { r[m0] = b; r[m1] = a; }
}

__device__ __forceinline__ void warp_merge(unsigned long long r[4], int base, int k, int jstart)
{
    for (int j = jstart; j >= 4; j >>= 1) {
        int d = j >> 2;                       // lane distance
        #pragma unroll
        for (int m = 0; m < 4; m++) {
            unsigned long long pv = __shfl_xor_sync(FULL, r[m], d);
            int i = base + m;
            bool keepmin = (((i & k) == 0) == ((i & j) == 0));
            bool pless   = pv < r[m];
            r[m] = (keepmin == pless) ? pv : r[m];
        }
    }
    bool a = ((base & k) == 0);               // uniform per thread for k >= 4
    cswap2(r, 0, 2, a); cswap2(r, 1, 3, a);
    cswap2(r, 0, 1, a); cswap2(r, 2, 3, a);
}

// ---------------- K2: sort runs + rank + scatter. One cluster of 8 CTAs per batch -----
__global__ __launch_bounds__(128) __cluster_dims__(NRUN, 1, 1) void k2_sortrank()
{
    int blk = blockIdx.x;                 // 0..31
    int b   = blk >> 3;
    int run = blk & 7;
    int tid = threadIdx.x;                // 128
    int base = tid * 4;                   // position within run
    int gbase = b*NN + run*RUN;

    __shared__ unsigned long long sp[RUN];

    // ---- phase 1: sort this CTA's 512-element run ----
    unsigned long long r[4];
    #pragma unroll
    for (int m = 0; m < 4; m++) {
        int i = base + m;
        unsigned u   = __float_as_uint(g_s2[gbase + i]);
        unsigned key = (u & 0x80000000u) ? ~u : (u | 0x80000000u);
        r[m] = ((unsigned long long)key << 32) | (unsigned)(run*RUN + i);
    }

    cswap2(r, 0, 1, true); cswap2(r, 2, 3, false);
    #pragma unroll
    for (int k = 4; k <= 128; k <<= 1)
        warp_merge(r, base, k, k >> 1);

    #pragma unroll
    for (int m = 0; m < 4; m++) sp[base + m] = r[m];
    __syncthreads();

    for (int k = 256; k <= RUN; k <<= 1) {
        for (int j = k >> 1; j >= 128; j >>= 1) {
            #pragma unroll
            for (int m = 0; m < 4; m++) {
                int i = base + m;
                int ixj = i ^ j;
                if (ixj > i) {
                    unsigned long long va = sp[i], vb = sp[ixj];
                    bool asc = ((i & k) == 0);
                    bool sw  = asc ? (va > vb) : (va < vb);
                    if (sw) { sp[i] = vb; sp[ixj] = va; }
                }
            }
            __syncthreads();
        }
        #pragma unroll
        for (int m = 0; m < 4; m++) r[m] = sp[base + m];
        warp_merge(r, base, k, 64);
        #pragma unroll
        for (int m = 0; m < 4; m++) sp[base + m] = r[m];
        __syncthreads();
    }

    #pragma unroll
    for (int m = 0; m < 4; m++) g_runs[gbase + base + m] = sp[base + m];

    // ---- cluster barrier: all 8 runs of this batch visible (sync flushes L1D) ----
    __threadfence();
    asm volatile("barrier.cluster.arrive.aligned;" ::: "memory");
    asm volatile("barrier.cluster.wait.aligned;"  ::: "memory");

    // ---- phase 2: rank via binary search + scatter (1024 cluster threads, 4 elems each) ----
    const unsigned long long* runs = g_runs + b*NN;

    // M2 = max over the 8 run tails
    unsigned long long mx = runs[RUN-1];
    #pragma unroll
    for (int r2 = 1; r2 < NRUN; r2++) {
        unsigned long long t = runs[r2*RUN + RUN-1];
        if (t > mx) mx = t;
    }
    unsigned hiM = (unsigned)(mx >> 32);
    unsigned uM  = (hiM & 0x80000000u) ? (hiM ^ 0x80000000u) : ~hiM;
    float M2 = __uint_as_float(uM);
    if (run == 0 && tid == 0) g_M2[b] = M2;

    int ct = run * 128 + tid;             // 0..1023 within cluster
    #pragma unroll
    for (int e = 0; e < 4; e++) {
        int pos  = ct * 4 + e;            // 0..4095
        int prun = pos >> 9;
        int loc  = pos & (RUN-1);

        unsigned long long pv = runs[pos];
        int rank = loc;
        #pragma unroll
        for (int r2 = 0; r2 < NRUN; r2++) {
            if (r2 == prun) continue;
            const unsigned long long* R = runs + r2*RUN;
            int lo = 0, hi = RUN;
            #pragma unroll
            for (int s = 0; s < 10; s++) {     // interval 512 -> 0 needs 10 halvings
                if (lo < hi) {
                    int mid = (lo + hi) >> 1;
                    if (R[mid] < pv) lo = mid + 1; else hi = mid;
                }
            }
            rank += lo;
        }

        unsigned hk = (unsigned)(pv >> 32);
        unsigned uv = (hk & 0x80000000u) ? (hk ^ 0x80000000u) : ~hk;
        float v = __uint_as_float(uv);

        g_sval[b*NN + rank] = v;
        g_sidx[b*NN + rank] = (int)(pv & 0xffffffffu);
        g_E1[b*NN + rank] = __expf(v - M2);
        g_E2[b*NN + rank] = __expf(ALPHA * v);
    }
}

// ---------------- K3a: chunk partial sums (grid = BB*G/8, block = 128) ----------------
__global__ __launch_bounds__(128) void k3a_partial()
{
    int tid = threadIdx.x;
    int rb  = tid >> 4;                    // chunk in block (0..7)
    int c4  = tid & 15;                    // float4 channel group
    int bg  = blockIdx.x * 8 + rb;         // b*G + g
    int b   = bg >> 9;                     // /G (G=512)
    int g   = bg & (G-1);
    int base = g * CH;

    const float4* hB4  = (const float4*)g_h + (size_t)b*NN*16;
    const int*    sidx = g_sidx + b*NN;
    const float*  E1   = g_E1   + b*NN;
    const float*  E2   = g_E2   + b*NN;

    float4 aL = make_float4(0.f,0.f,0.f,0.f);
    float4 aG = make_float4(0.f,0.f,0.f,0.f);
    #pragma unroll
    for (int k = base; k < base + CH; k++) {
        float4 hv = hB4[(size_t)sidx[k]*16 + c4];
        float e2 = E2[k], e1 = E1[k];
        aL.x = fmaf(e2, hv.x, aL.x); aL.y = fmaf(e2, hv.y, aL.y);
        aL.z = fmaf(e2, hv.z, aL.z); aL.w = fmaf(e2, hv.w, aL.w);
        aG.x = fmaf(e1, hv.x, aG.x); aG.y = fmaf(e1, hv.y, aG.y);
        aG.z = fmaf(e1, hv.z, aG.z); aG.w = fmaf(e1, hv.w, aG.w);
    }
    ((float4*)g_pl)[(size_t)bg*16 + c4] = aL;
    ((float4*)g_pg)[(size_t)bg*16 + c4] = aG;
}

// ---------------- K3b: warp-shuffle scans over G=512 chunk partials ----------------
__device__ __forceinline__ float4 warp_iscan4(float4 v, int lane)
{
    #pragma unroll
    for (int o = 1; o < 32; o <<= 1) {
        float ux = __shfl_up_sync(FULL, v.x, o);
        float uy = __shfl_up_sync(FULL, v.y, o);
        float uz = __shfl_up_sync(FULL, v.z, o);
        float uw = __shfl_up_sync(FULL, v.w, o);
        if (lane >= o) { v.x += ux; v.y += uy; v.z += uz; v.w += uw; }
    }
    return v;
}
__device__ __forceinline__ float warp_iscan1(float v, int lane)
{
    #pragma unroll
    for (int o = 1; o < 32; o <<= 1) {
        float u = __shfl_up_sync(FULL, v, o);
        if (lane >= o) v += u;
    }
    return v;
}

// grid = BB*17: 16 float4-channel-group blocks + 1 scalar block per batch. block=512.
__global__ __launch_bounds__(512) void k3b_offsets()
{
    int bx = blockIdx.x;
    int b  = bx / 17;
    int cg = bx % 17;
    int t  = threadIdx.x;                 // 0..511 (one per chunk)
    int lane = t & 31, w = t >> 5;        // 16 warps

    __shared__ float4 ws4[16];

    if (cg < 16) {
        // prefix over pl
        float4 pl = ((const float4*)g_pl)[(size_t)(b*G + t)*16 + cg];
        float4 v = warp_iscan4(pl, lane);
        if (lane == 31) ws4[w] = v;
        __syncthreads();
        float4 off = make_float4(0.f,0.f,0.f,0.f);
        for (int i = 0; i < w; i++) {
            float4 s = ws4[i];
            off.x += s.x; off.y += s.y; off.z += s.z; off.w += s.w;
        }
        float4 ofL = make_float4(v.x+off.x-pl.x, v.y+off.y-pl.y,
                                 v.z+off.z-pl.z, v.w+off.w-pl.w);
        ((float4*)g_ofL)[(size_t)(b*G + t)*16 + cg] = ofL;
        __syncthreads();

        // suffix over pg: scan reversed order
        int gr = G - 1 - t;
        float4 pg = ((const float4*)g_pg)[(size_t)(b*G + gr)*16 + cg];
        v = warp_iscan4(pg, lane);
        if (lane == 31) ws4[w] = v;
        __syncthreads();
        off = make_float4(0.f,0.f,0.f,0.f);
        for (int i = 0; i < w; i++) {
            float4 s = ws4[i];
            off.x += s.x; off.y += s.y; off.z += s.z; off.w += s.w;
        }
        float4 ofG = make_float4(v.x+off.x-pg.x, v.y+off.y-pg.y,
                                 v.z+off.z-pg.z, v.w+off.w-pg.w);
        ((float4*)g_ofG)[(size_t)(b*G + gr)*16 + cg] = ofG;
    } else {
        float* wss = (float*)ws4;
        const float4* E2v = (const float4*)(g_E2 + b*NN);
        const float4* E1v = (const float4*)(g_E1 + b*NN);

        // prefix of per-chunk E2 sums (chunk t)
        float pls = 0.f;
        #pragma unroll
        for (int m = 0; m < CH/4; m++) {
            float4 e2 = E2v[t*(CH/4) + m];
            pls += (e2.x + e2.y) + (e2.z + e2.w);
        }
        float v = warp_iscan1(pls, lane);
        if (lane == 31) wss[w] = v;
        __syncthreads();
        float off = 0.f;
        for (int i = 0; i < w; i++) off += wss[i];
        g_ofLs[b*G + t] = v + off - pls;
        __syncthreads();

        // suffix of per-chunk E1 sums (chunk gr)
        int gr = G - 1 - t;
        float pgs = 0.f;
        #pragma unroll
        for (int m = 0; m < CH/4; m++) {
            float4 e1 = E1v[gr*(CH/4) + m];
            pgs += (e1.x + e1.y) + (e1.z + e1.w);
        }
        v = warp_iscan1(pgs, lane);
        if (lane == 31) wss[w] = v;
        __syncthreads();
        off = 0.f;
        for (int i = 0; i < w; i++) off += wss[i];
        g_ofGs[b*G + gr] = v + off - pgs;
    }
}

// ---------------- K3c: write scan tables. grid = 2*BB*G/8: first half prefix, second suffix ----
__global__ __launch_bounds__(128) void k3c_tables()
{
    const int half = BB*G/8;              // 256 blocks per role
    bool suffix = (blockIdx.x >= half);
    int blk = suffix ? (blockIdx.x - half) : blockIdx.x;

    int tid = threadIdx.x;
    int rb  = tid >> 4;
    int c4  = tid & 15;
    int bg  = blk * 8 + rb;
    int b   = bg >> 9;                    // /G (G=512)
    int g   = bg & (G-1);
    int base = g * CH;

    const float4* hB4  = (const float4*)g_h + (size_t)b*NN*16;
    const int*    sidx = g_sidx + b*NN;

    if (!suffix) {
        const float* E2 = g_E2 + b*NN;
        float4* SltH4 = (float4*)g_SltH + (size_t)b*(NN+1)*16;
        float*  Slt1  = g_Slt1 + b*(NN+1);
        float4 acc  = ((const float4*)g_ofL)[(size_t)bg*16 + c4];
        float  accs = g_ofLs[bg];
        #pragma unroll
        for (int k = base; k < base + CH; k++) {
            SltH4[(size_t)k*16 + c4] = acc;
            if (c4 == 0) Slt1[k] = accs;
            float  e2 = E2[k];
            float4 hv = hB4[(size_t)sidx[k]*16 + c4];
            acc.x = fmaf(e2, hv.x, acc.x); acc.y = fmaf(e2, hv.y, acc.y);
            acc.z = fmaf(e2, hv.z, acc.z); acc.w = fmaf(e2, hv.w, acc.w);
            accs += e2;
        }
        if (g == G-1) {
            SltH4[(size_t)NN*16 + c4] = acc;
            if (c4 == 0) Slt1[NN] = accs;
        }
    } else {
        const float* E1 = g_E1 + b*NN;
        float4* SgeH4 = (float4*)g_SgeH + (size_t)b*(NN+1)*16;
        float*  Sge1  = g_Sge1 + b*(NN+1);
        float4 acc  = ((const float4*)g_ofG)[(size_t)bg*16 + c4];
        float  accs = g_ofGs[bg];
        if (g == G-1) {
            SgeH4[(size_t)NN*16 + c4] = make_float4(0.f,0.f,0.f,0.f);
            if (c4 == 0) Sge1[NN] = 0.f;
        }
        #pragma unroll
        for (int k = base + CH - 1; k >= base; k--) {
            float  e1 = E1[k];
            float4 hv = hB4[(size_t)sidx[k]*16 + c4];
            acc.x = fmaf(e1, hv.x, acc.x); acc.y = fmaf(e1, hv.y, acc.y);
            acc.z = fmaf(e1, hv.z, acc.z); acc.w = fmaf(e1, hv.w, acc.w);
            accs += e1;
            SgeH4[(size_t)k*16 + c4] = acc;
            if (c4 == 0) Sge1[k] = accs;
        }
    }
}

// ---------------- K4: per-row threshold lookup + combine ----------------
__global__ void k4_out(float* __restrict__ out)
{
    int gw   = (blockIdx.x * blockDim.x + threadIdx.x) >> 5;
    int lane = threadIdx.x & 31;
    if (gw >= BB*NN) return;
    int b = gw >> 12;

    float s1v = g_s1[gw];
    float M2  = g_M2[b];
    float thr = -s1v;

    const float* sval = g_sval + b*NN;
    int lo = 0, hi = NN;
    while (lo < hi) {
        int mid = (lo + hi) >> 1;
        if (sval[mid] < thr) lo = mid + 1; else hi = mid;
    }
    int k = lo;

    float x = s1v + M2;
    float m = (x >= 0.f) ? x : ALPHA * x;       // row max of lrelu logits
    float cge = __expf(x - m);                  // pairs with E1 = exp(s2 - M2)
    float clt = __expf(ALPHA * s1v - m);        // pairs with E2 = exp(alpha*s2)

    const float* SgeH = g_SgeH + ((size_t)b*(NN+1) + k)*64;
    const float* SltH = g_SltH + ((size_t)b*(NN+1) + k)*64;
    float denom = cge * g_Sge1[b*(NN+1) + k] + clt * g_Slt1[b*(NN+1) + k];
    float inv = 1.f / denom;

    float ge0 = SgeH[2*lane],   ge1 = SgeH[2*lane+1];
    float lt0 = SltH[2*lane],   lt1 = SltH[2*lane+1];
    float o0 = (cge*ge0 + clt*lt0) * inv;
    float o1 = (cge*ge1 + clt*lt1) * inv;

    float2* op = (float2*)(out + (size_t)gw*64);
    op[lane] = make_float2(o0, o1);
}

// ---------------- launch ----------------
extern "C" void kernel_launch(void* const* d_in, const int* in_sizes, int n_in,
                              void* d_out, int out_size)
{
    const float* feat = (const float*)d_in[0];
    // d_in[1] = adj: unused by the reference computation — deliberately not read.
    const float* W    = (const float*)d_in[2];
    const float* a    = (const float*)d_in[3];
    float* out = (float*)d_out;

    k1_hsw<<<(BB*NN)/16, 256>>>(feat, W, a);
    k2_sortrank<<<BB*NRUN, 128>>>();
    k3a_partial<<<BB*G/8, 128>>>();
    k3b_offsets<<<BB*17, 512>>>();
    k3c_tables<<<2*BB*G/8, 128>>>();
    k4_out<<<(BB*NN*32)/256, 256>>>(out);
}

// round 12
// speedup vs baseline: 1.1370x; 1.1370x over previous
#include <cuda_runtime.h>
#include <math.h>

#define BB 4
#define NN 4096
#define CC 64
#define ALPHA 0.2f
#define G  256          // scan chunks per batch
#define CH 16           // elements per chunk (NN = G*CH)
#define RUN 512         // sort run length
#define NRUN 8          // runs per batch
#define FULL 0xffffffffu

// ---------------- scratch (static device globals; no allocation) ----------------
__device__ __align__(16) float g_h[BB*NN*CC];        // h = feat @ W
__device__ __align__(16) float g_s1[BB*NN];
__device__ __align__(16) float g_s2[BB*NN];
__device__ float g_M2[BB];
__device__ __align__(16) float g_sval[BB*NN];        // sorted s2 (ascending) per batch
__device__ __align__(16) int   g_sidx[BB*NN];        // permutation
__device__ __align__(16) float g_E1[BB*NN];          // exp(sval - M2)
__device__ __align__(16) float g_E2[BB*NN];          // exp(alpha * sval)
__device__ __align__(16) unsigned long long g_runs[BB*NN]; // sorted runs (packed key|idx)
__device__ __align__(16) float g_SgeH[BB*(NN+1)*CC]; // suffix sums of E1*h
__device__ __align__(16) float g_SltH[BB*(NN+1)*CC]; // prefix sums of E2*h
__device__ __align__(16) float g_Sge1[BB*(NN+1)];
__device__ __align__(16) float g_Slt1[BB*(NN+1)];
// scan intermediates
__device__ __align__(16) float g_pl [BB*G*CC], g_pg [BB*G*CC];  // chunk partials
__device__ __align__(16) float g_ofL[BB*G*CC], g_ofG[BB*G*CC];  // chunk offsets
__device__ float g_ofLs[BB*G], g_ofGs[BB*G];                    // scalar offsets

// ---------------- K1: h = feat @ W, s1 = h.a1, s2 = h.a2 ----------------
__global__ __launch_bounds__(256) void k1_hsw(const float* __restrict__ feat,
                                              const float* __restrict__ W,
                                              const float* __restrict__ a)
{
    __shared__ float Ws[64*64];
    __shared__ float a1s[64], a2s[64];
    __shared__ float fs[4][64];
    __shared__ float p1[4][2], p2[4][2];

    int tid = threadIdx.x;                 // 256
    for (int i = tid; i < 64*64; i += 256) Ws[i] = W[i];
    if (tid < 64) { a1s[tid] = a[tid]; a2s[tid] = a[64 + tid]; }

    int rb = tid >> 6;                     // 0..3
    int c  = tid & 63;

    #pragma unroll
    for (int r = 0; r < 4; r++) {
        int row = blockIdx.x * 16 + r * 4 + rb;
        fs[rb][c] = feat[row*64 + c];
        __syncthreads();

        float acc0 = 0.f, acc1 = 0.f;
        #pragma unroll
        for (int k = 0; k < 64; k += 2) {
            acc0 = fmaf(fs[rb][k],   Ws[k*64 + c],     acc0);
            acc1 = fmaf(fs[rb][k+1], Ws[(k+1)*64 + c], acc1);
        }
        float acc = acc0 + acc1;
        g_h[row*64 + c] = acc;

        float v1 = acc * a1s[c];
        float v2 = acc * a2s[c];
        #pragma unroll
        for (int o = 16; o > 0; o >>= 1) {
            v1 += __shfl_down_sync(FULL, v1, o);
            v2 += __shfl_down_sync(FULL, v2, o);
        }
        if ((c & 31) == 0) { p1[rb][c>>5] = v1; p2[rb][c>>5] = v2; }
        __syncthreads();
        if (c == 0) {
            g_s1[row] = p1[rb][0] + p1[rb][1];
            g_s2[row] = p2[rb][0] + p2[rb][1];
        }
    }
}

// ---------------- bitonic helpers (packed u64 key|idx) ----------------
__device__ __forceinline__ void cswap2(unsigned long long r[4], int m0, int m1, bool asc)
{
    unsigned long long a = r[m0], b = r[m1];
    bool sw = asc ? (a > b) : (a < b);
    if (sw) { r[m0] = b; r[m1] = a; }
}

__device__ __forceinline__ void warp_merge(unsigned long long r[4], int base, int k, int jstart)
{
    for (int j = jstart; j >= 4; j >>= 1) {
        int d = j >> 2;                       // lane distance
        #pragma unroll
        for (int m = 0; m < 4; m++) {
            unsigned long long pv = __shfl_xor_sync(FULL, r[m], d);
            int i = base + m;
            bool keepmin = (((i & k) == 0) == ((i & j) == 0));
            bool pless   = pv < r[m];
            r[m] = (keepmin == pless) ? pv : r[m];
        }
    }
    bool a = ((base & k) == 0);               // uniform per thread for k >= 4
    cswap2(r, 0, 2, a); cswap2(r, 1, 3, a);
    cswap2(r, 0, 1, a); cswap2(r, 2, 3, a);
}

// ---------------- K2a: sort 512-element runs (grid = BB*NRUN, block = 128) -------------
__global__ __launch_bounds__(128) void k2a_sort_runs()
{
    int blk = blockIdx.x;                 // 0..31
    int b   = blk >> 3;
    int run = blk & 7;
    int tid = threadIdx.x;                // 128
    int base = tid * 4;                   // position within run
    int gbase = b*NN + run*RUN;

    __shared__ unsigned long long sp[RUN];

    unsigned long long r[4];
    #pragma unroll
    for (int m = 0; m < 4; m++) {
        int i = base + m;
        unsigned u   = __float_as_uint(g_s2[gbase + i]);
        unsigned key = (u & 0x80000000u) ? ~u : (u | 0x80000000u);
        r[m] = ((unsigned long long)key << 32) | (unsigned)(run*RUN + i);
    }

    // stages k=2..128 in registers / shuffles
    cswap2(r, 0, 1, true); cswap2(r, 2, 3, false);
    #pragma unroll
    for (int k = 4; k <= 128; k <<= 1)
        warp_merge(r, base, k, k >> 1);

    #pragma unroll
    for (int m = 0; m < 4; m++) sp[base + m] = r[m];
    __syncthreads();

    // stages k=256, 512: smem for j>=128, register tail
    for (int k = 256; k <= RUN; k <<= 1) {
        for (int j = k >> 1; j >= 128; j >>= 1) {
            #pragma unroll
            for (int m = 0; m < 4; m++) {
                int i = base + m;
                int ixj = i ^ j;
                if (ixj > i) {
                    unsigned long long va = sp[i], vb = sp[ixj];
                    bool asc = ((i & k) == 0);
                    bool sw  = asc ? (va > vb) : (va < vb);
                    if (sw) { sp[i] = vb; sp[ixj] = va; }
                }
            }
            __syncthreads();
        }
        #pragma unroll
        for (int m = 0; m < 4; m++) r[m] = sp[base + m];
        warp_merge(r, base, k, 64);
        #pragma unroll
        for (int m = 0; m < 4; m++) sp[base + m] = r[m];
        __syncthreads();
    }

    #pragma unroll
    for (int m = 0; m < 4; m++) g_runs[gbase + base + m] = sp[base + m];
}

// ---------------- K2b: global rank via binary search + scatter (grid = BB*NN/256) ------
__global__ __launch_bounds__(256) void k2b_rank()
{
    int gid = blockIdx.x * 256 + threadIdx.x;   // 0..BB*NN-1
    int b   = gid >> 12;
    int pos = gid & (NN-1);
    int run = pos >> 9;
    int loc = pos & (RUN-1);

    const unsigned long long* runs = g_runs + b*NN;
    unsigned long long pv = runs[pos];

    int rank = loc;
    #pragma unroll
    for (int r2 = 0; r2 < NRUN; r2++) {
        if (r2 == run) continue;
        const unsigned long long* R = runs + r2*RUN;
        int lo = 0, hi = RUN;
        #pragma unroll
        for (int s = 0; s < 10; s++) {         // interval 512 -> 0 needs 10 halvings
            if (lo < hi) {
                int mid = (lo + hi) >> 1;
                if (R[mid] < pv) lo = mid + 1; else hi = mid;
            }
        }
        rank += lo;
    }

    // M2 = max over the 8 run tails
    unsigned long long mx = runs[RUN-1];
    #pragma unroll
    for (int r2 = 1; r2 < NRUN; r2++) {
        unsigned long long t = runs[r2*RUN + RUN-1];
        if (t > mx) mx = t;
    }
    unsigned hiM = (unsigned)(mx >> 32);
    unsigned uM  = (hiM & 0x80000000u) ? (hiM ^ 0x80000000u) : ~hiM;
    float M2 = __uint_as_float(uM);
    if (pos == 0) g_M2[b] = M2;

    unsigned hk = (unsigned)(pv >> 32);
    unsigned uv = (hk & 0x80000000u) ? (hk ^ 0x80000000u) : ~hk;
    float v = __uint_as_float(uv);

    g_sval[b*NN + rank] = v;
    g_sidx[b*NN + rank] = (int)(pv & 0xffffffffu);
    g_E1[b*NN + rank] = __expf(v - M2);
    g_E2[b*NN + rank] = __expf(ALPHA * v);
}

// ---------------- K3a: chunk partial sums, one warp per chunk (grid = BB*G/8, block=256) ----
// Warp = 16 float4 channel-groups x 2 halves of the chunk; halves combined via shfl.
__global__ __launch_bounds__(256) void k3a_partial()
{
    int tid  = threadIdx.x;
    int wrp  = tid >> 5;                   // chunk in block (0..7)
    int lane = tid & 31;
    int half = lane >> 4;                  // 0/1
    int c4   = lane & 15;                  // float4 channel group
    int bg   = blockIdx.x * 8 + wrp;       // b*G + g
    int b    = bg >> 8;
    int g    = bg & (G-1);
    int base = g * CH + half * (CH/2);

    const float4* hB4  = (const float4*)g_h + (size_t)b*NN*16;
    const int*    sidx = g_sidx + b*NN;
    const float*  E1   = g_E1   + b*NN;
    const float*  E2   = g_E2   + b*NN;

    float4 aL = make_float4(0.f,0.f,0.f,0.f);
    float4 aG = make_float4(0.f,0.f,0.f,0.f);
    #pragma unroll
    for (int k = base; k < base + CH/2; k++) {
        float4 hv = hB4[(size_t)sidx[k]*16 + c4];
        float e2 = E2[k], e1 = E1[k];
        aL.x = fmaf(e2, hv.x, aL.x); aL.y = fmaf(e2, hv.y, aL.y);
        aL.z = fmaf(e2, hv.z, aL.z); aL.w = fmaf(e2, hv.w, aL.w);
        aG.x = fmaf(e1, hv.x, aG.x); aG.y = fmaf(e1, hv.y, aG.y);
        aG.z = fmaf(e1, hv.z, aG.z); aG.w = fmaf(e1, hv.w, aG.w);
    }
    // combine halves (lane and lane+16)
    aL.x += __shfl_down_sync(FULL, aL.x, 16);
    aL.y += __shfl_down_sync(FULL, aL.y, 16);
    aL.z += __shfl_down_sync(FULL, aL.z, 16);
    aL.w += __shfl_down_sync(FULL, aL.w, 16);
    aG.x += __shfl_down_sync(FULL, aG.x, 16);
    aG.y += __shfl_down_sync(FULL, aG.y, 16);
    aG.z += __shfl_down_sync(FULL, aG.z, 16);
    aG.w += __shfl_down_sync(FULL, aG.w, 16);
    if (half == 0) {
        ((float4*)g_pl)[(size_t)bg*16 + c4] = aL;
        ((float4*)g_pg)[(size_t)bg*16 + c4] = aG;
    }
}

// ---------------- K3b: warp-shuffle scans over G=256 chunk partials ----------------
__device__ __forceinline__ float4 warp_iscan4(float4 v, int lane)
{
    #pragma unroll
    for (int o = 1; o < 32; o <<= 1) {
        float ux = __shfl_up_sync(FULL, v.x, o);
        float uy = __shfl_up_sync(FULL, v.y, o);
        float uz = __shfl_up_sync(FULL, v.z, o);
        float uw = __shfl_up_sync(FULL, v.w, o);
        if (lane >= o) { v.x += ux; v.y += uy; v.z += uz; v.w += uw; }
    }
    return v;
}
__device__ __forceinline__ float warp_iscan1(float v, int lane)
{
    #pragma unroll
    for (int o = 1; o < 32; o <<= 1) {
        float u = __shfl_up_sync(FULL, v, o);
        if (lane >= o) v += u;
    }
    return v;
}

// grid = BB*17: 16 float4-channel-group blocks + 1 scalar block per batch. block=256.
__global__ __launch_bounds__(256) void k3b_offsets()
{
    int bx = blockIdx.x;
    int b  = bx / 17;
    int cg = bx % 17;
    int t  = threadIdx.x;                 // 0..255 (one per chunk)
    int lane = t & 31, w = t >> 5;        // 8 warps

    __shared__ float4 ws4[8];

    if (cg < 16) {
        // prefix over pl
        float4 pl = ((const float4*)g_pl)[(size_t)(b*G + t)*16 + cg];
        float4 v = warp_iscan4(pl, lane);
        if (lane == 31) ws4[w] = v;
        __syncthreads();
        float4 off = make_float4(0.f,0.f,0.f,0.f);
        for (int i = 0; i < w; i++) {
            float4 s = ws4[i];
            off.x += s.x; off.y += s.y; off.z += s.z; off.w += s.w;
        }
        float4 ofL = make_float4(v.x+off.x-pl.x, v.y+off.y-pl.y,
                                 v.z+off.z-pl.z, v.w+off.w-pl.w);
        ((float4*)g_ofL)[(size_t)(b*G + t)*16 + cg] = ofL;
        __syncthreads();

        // suffix over pg: scan reversed order
        int gr = G - 1 - t;
        float4 pg = ((const float4*)g_pg)[(size_t)(b*G + gr)*16 + cg];
        v = warp_iscan4(pg, lane);
        if (lane == 31) ws4[w] = v;
        __syncthreads();
        off = make_float4(0.f,0.f,0.f,0.f);
        for (int i = 0; i < w; i++) {
            float4 s = ws4[i];
            off.x += s.x; off.y += s.y; off.z += s.z; off.w += s.w;
        }
        float4 ofG = make_float4(v.x+off.x-pg.x, v.y+off.y-pg.y,
                                 v.z+off.z-pg.z, v.w+off.w-pg.w);
        ((float4*)g_ofG)[(size_t)(b*G + gr)*16 + cg] = ofG;
    } else {
        float* wss = (float*)ws4;
        const float4* E2v = (const float4*)(g_E2 + b*NN);
        const float4* E1v = (const float4*)(g_E1 + b*NN);

        // prefix of per-chunk E2 sums (chunk t)
        float pls = 0.f;
        #pragma unroll
        for (int m = 0; m < CH/4; m++) {
            float4 e2 = E2v[t*(CH/4) + m];
            pls += (e2.x + e2.y) + (e2.z + e2.w);
        }
        float v = warp_iscan1(pls, lane);
        if (lane == 31) wss[w] = v;
        __syncthreads();
        float off = 0.f;
        for (int i = 0; i < w; i++) off += wss[i];
        g_ofLs[b*G + t] = v + off - pls;
        __syncthreads();

        // suffix of per-chunk E1 sums (chunk gr)
        int gr = G - 1 - t;
        float pgs = 0.f;
        #pragma unroll
        for (int m = 0; m < CH/4; m++) {
            float4 e1 = E1v[gr*(CH/4) + m];
            pgs += (e1.x + e1.y) + (e1.z + e1.w);
        }
        v = warp_iscan1(pgs, lane);
        if (lane == 31) wss[w] = v;
        __syncthreads();
        off = 0.f;
        for (int i = 0; i < w; i++) off += wss[i];
        g_ofGs[b*G + gr] = v + off - pgs;
    }
}

// ---------------- K3c: write scan tables. grid = 2*BB*G/8: first half prefix, second suffix ----
__global__ __launch_bounds__(128) void k3c_tables()
{
    const int half = BB*G/8;              // 128 blocks per role
    bool suffix = (blockIdx.x >= half);
    int blk = suffix ? (blockIdx.x - half) : blockIdx.x;

    int tid = threadIdx.x;
    int rb  = tid >> 4;
    int c4  = tid & 15;
    int bg  = blk * 8 + rb;
    int b   = bg >> 8;
    int g   = bg & (G-1);
    int base = g * CH;

    const float4* hB4  = (const float4*)g_h + (size_t)b*NN*16;
    const int*    sidx = g_sidx + b*NN;

    if (!suffix) {
        const float* E2 = g_E2 + b*NN;
        float4* SltH4 = (float4*)g_SltH + (size_t)b*(NN+1)*16;
        float*  Slt1  = g_Slt1 + b*(NN+1);
        float4 acc  = ((const float4*)g_ofL)[(size_t)bg*16 + c4];
        float  accs = g_ofLs[bg];
        #pragma unroll
        for (int k = base; k < base + CH; k++) {
            SltH4[(size_t)k*16 + c4] = acc;
            if (c4 == 0) Slt1[k] = accs;
            float  e2 = E2[k];
            float4 hv = hB4[(size_t)sidx[k]*16 + c4];
            acc.x = fmaf(e2, hv.x, acc.x); acc.y = fmaf(e2, hv.y, acc.y);
            acc.z = fmaf(e2, hv.z, acc.z); acc.w = fmaf(e2, hv.w, acc.w);
            accs += e2;
        }
        if (g == G-1) {
            SltH4[(size_t)NN*16 + c4] = acc;
            if (c4 == 0) Slt1[NN] = accs;
        }
    } else {
        const float* E1 = g_E1 + b*NN;
        float4* SgeH4 = (float4*)g_SgeH + (size_t)b*(NN+1)*16;
        float*  Sge1  = g_Sge1 + b*(NN+1);
        float4 acc  = ((const float4*)g_ofG)[(size_t)bg*16 + c4];
        float  accs = g_ofGs[bg];
        if (g == G-1) {
            SgeH4[(size_t)NN*16 + c4] = make_float4(0.f,0.f,0.f,0.f);
            if (c4 == 0) Sge1[NN] = 0.f;
        }
        #pragma unroll
        for (int k = base + CH - 1; k >= base; k--) {
            float  e1 = E1[k];
            float4 hv = hB4[(size_t)sidx[k]*16 + c4];
            acc.x = fmaf(e1, hv.x, acc.x); acc.y = fmaf(e1, hv.y, acc.y);
            acc.z = fmaf(e1, hv.z, acc.z); acc.w = fmaf(e1, hv.w, acc.w);
            accs += e1;
            SgeH4[(size_t)k*16 + c4] = acc;
            if (c4 == 0) Sge1[k] = accs;
        }
    }
}

// ---------------- K4: per-row threshold lookup + combine ----------------
__global__ void k4_out(float* __restrict__ out)
{
    int gw   = (blockIdx.x * blockDim.x + threadIdx.x) >> 5;
    int lane = threadIdx.x & 31;
    if (gw >= BB*NN) return;
    int b = gw >> 12;

    float s1v = g_s1[gw];
    float M2  = g_M2[b];
    float thr = -s1v;

    const float* sval = g_sval + b*NN;
    int lo = 0, hi = NN;
    while (lo < hi) {
        int mid = (lo + hi) >> 1;
        if (sval[mid] < thr) lo = mid + 1; else hi = mid;
    }
    int k = lo;

    float x = s1v + M2;
    float m = (x >= 0.f) ? x : ALPHA * x;       // row max of lrelu logits
    float cge = __expf(x - m);                  // pairs with E1 = exp(s2 - M2)
    float clt = __expf(ALPHA * s1v - m);        // pairs with E2 = exp(alpha*s2)

    const float* SgeH = g_SgeH + ((size_t)b*(NN+1) + k)*64;
    const float* SltH = g_SltH + ((size_t)b*(NN+1) + k)*64;
    float denom = cge * g_Sge1[b*(NN+1) + k] + clt * g_Slt1[b*(NN+1) + k];
    float inv = 1.f / denom;

    float ge0 = SgeH[2*lane],   ge1 = SgeH[2*lane+1];
    float lt0 = SltH[2*lane],   lt1 = SltH[2*lane+1];
    float o0 = (cge*ge0 + clt*lt0) * inv;
    float o1 = (cge*ge1 + clt*lt1) * inv;

    float2* op = (float2*)(out + (size_t)gw*64);
    op[lane] = make_float2(o0, o1);
}

// ---------------- launch ----------------
extern "C" void kernel_launch(void* const* d_in, const int* in_sizes, int n_in,
                              void* d_out, int out_size)
{
    const float* feat = (const float*)d_in[0];
    // d_in[1] = adj: unused by the reference computation — deliberately not read.
    const float* W    = (const float*)d_in[2];
    const float* a    = (const float*)d_in[3];
    float* out = (float*)d_out;

    k1_hsw<<<(BB*NN)/16, 256>>>(feat, W, a);
    k2a_sort_runs<<<BB*NRUN, 128>>>();
    k2b_rank<<<BB*NN/256, 256>>>();
    k3a_partial<<<BB*G/8, 256>>>();
    k3b_offsets<<<BB*17, 256>>>();
    k3c_tables<<<2*BB*G/8, 128>>>();
    k4_out<<<(BB*NN*32)/256, 256>>>(out);
}

// round 13
// speedup vs baseline: 1.2116x; 1.0656x over previous
#include <cuda_runtime.h>
#include <math.h>

#define BB 4
#define NN 4096
#define CC 64
#define ALPHA 0.2f
#define G  256          // scan chunks per batch
#define CH 16           // elements per chunk (NN = G*CH)
#define RUN 512         // sort run length
#define NRUN 8          // runs per batch
#define FULL 0xffffffffu

// ---------------- scratch (static device globals; no allocation) ----------------
__device__ __align__(16) float g_h[BB*NN*CC];        // h = feat @ W
__device__ __align__(16) float g_s1[BB*NN];
__device__ __align__(16) float g_s2[BB*NN];
__device__ float g_M2[BB];
__device__ __align__(16) float g_sval[BB*NN];        // sorted s2 (ascending) per batch
__device__ __align__(16) int   g_sidx[BB*NN];        // permutation
__device__ __align__(16) float g_E1[BB*NN];          // exp(sval - M2)
__device__ __align__(16) float g_E2[BB*NN];          // exp(alpha * sval)
__device__ __align__(16) unsigned long long g_runs[BB*NN]; // sorted runs (packed key|idx)
// scan intermediates
__device__ __align__(16) float g_pl [BB*G*CC], g_pg [BB*G*CC];        // chunk partials
__device__ __align__(16) float g_ofL[BB*(G+1)*CC], g_ofG[BB*(G+1)*CC]; // chunk offsets (+boundary)
__device__ float g_ofLs[BB*(G+1)], g_ofGs[BB*(G+1)];                   // scalar offsets

// ---------------- K1: h = feat @ W, s1 = h.a1, s2 = h.a2 ----------------
__global__ __launch_bounds__(256) void k1_hsw(const float* __restrict__ feat,
                                              const float* __restrict__ W,
                                              const float* __restrict__ a)
{
    __shared__ float Ws[64*64];
    __shared__ float a1s[64], a2s[64];
    __shared__ float fs[4][64];
    __shared__ float p1[4][2], p2[4][2];

    int tid = threadIdx.x;                 // 256
    for (int i = tid; i < 64*64; i += 256) Ws[i] = W[i];
    if (tid < 64) { a1s[tid] = a[tid]; a2s[tid] = a[64 + tid]; }

    int rb = tid >> 6;                     // 0..3
    int c  = tid & 63;

    #pragma unroll
    for (int r = 0; r < 4; r++) {
        int row = blockIdx.x * 16 + r * 4 + rb;
        fs[rb][c] = feat[row*64 + c];
        __syncthreads();

        float acc0 = 0.f, acc1 = 0.f;
        #pragma unroll
        for (int k = 0; k < 64; k += 2) {
            acc0 = fmaf(fs[rb][k],   Ws[k*64 + c],     acc0);
            acc1 = fmaf(fs[rb][k+1], Ws[(k+1)*64 + c], acc1);
        }
        float acc = acc0 + acc1;
        g_h[row*64 + c] = acc;

        float v1 = acc * a1s[c];
        float v2 = acc * a2s[c];
        #pragma unroll
        for (int o = 16; o > 0; o >>= 1) {
            v1 += __shfl_down_sync(FULL, v1, o);
            v2 += __shfl_down_sync(FULL, v2, o);
        }
        if ((c & 31) == 0) { p1[rb][c>>5] = v1; p2[rb][c>>5] = v2; }
        __syncthreads();
        if (c == 0) {
            g_s1[row] = p1[rb][0] + p1[rb][1];
            g_s2[row] = p2[rb][0] + p2[rb][1];
        }
    }
}

// ---------------- bitonic helpers (packed u64 key|idx) ----------------
__device__ __forceinline__ void cswap2(unsigned long long r[4], int m0, int m1, bool asc)
{
    unsigned long long a = r[m0], b = r[m1];
    bool sw = asc ? (a > b) : (a < b);
    if (sw) { r[m0] = b; r[m1] = a; }
}

__device__ __forceinline__ void warp_merge(unsigned long long r[4], int base, int k, int jstart)
{
    for (int j = jstart; j >= 4; j >>= 1) {
        int d = j >> 2;                       // lane distance
        #pragma unroll
        for (int m = 0; m < 4; m++) {
            unsigned long long pv = __shfl_xor_sync(FULL, r[m], d);
            int i = base + m;
            bool keepmin = (((i & k) == 0) == ((i & j) == 0));
            bool pless   = pv < r[m];
            r[m] = (keepmin == pless) ? pv : r[m];
        }
    }
    bool a = ((base & k) == 0);               // uniform per thread for k >= 4
    cswap2(r, 0, 2, a); cswap2(r, 1, 3, a);
    cswap2(r, 0, 1, a); cswap2(r, 2, 3, a);
}

// ---------------- K2a: sort 512-element runs (grid = BB*NRUN, block = 128) -------------
__global__ __launch_bounds__(128) void k2a_sort_runs()
{
    int blk = blockIdx.x;                 // 0..31
    int b   = blk >> 3;
    int run = blk & 7;
    int tid = threadIdx.x;                // 128
    int base = tid * 4;                   // position within run
    int gbase = b*NN + run*RUN;

    __shared__ unsigned long long sp[RUN];

    unsigned long long r[4];
    #pragma unroll
    for (int m = 0; m < 4; m++) {
        int i = base + m;
        unsigned u   = __float_as_uint(g_s2[gbase + i]);
        unsigned key = (u & 0x80000000u) ? ~u : (u | 0x80000000u);
        r[m] = ((unsigned long long)key << 32) | (unsigned)(run*RUN + i);
    }

    // stages k=2..128 in registers / shuffles
    cswap2(r, 0, 1, true); cswap2(r, 2, 3, false);
    #pragma unroll
    for (int k = 4; k <= 128; k <<= 1)
        warp_merge(r, base, k, k >> 1);

    #pragma unroll
    for (int m = 0; m < 4; m++) sp[base + m] = r[m];
    __syncthreads();

    // stages k=256, 512: smem for j>=128, register tail
    for (int k = 256; k <= RUN; k <<= 1) {
        for (int j = k >> 1; j >= 128; j >>= 1) {
            #pragma unroll
            for (int m = 0; m < 4; m++) {
                int i = base + m;
                int ixj = i ^ j;
                if (ixj > i) {
                    unsigned long long va = sp[i], vb = sp[ixj];
                    bool asc = ((i & k) == 0);
                    bool sw  = asc ? (va > vb) : (va < vb);
                    if (sw) { sp[i] = vb; sp[ixj] = va; }
                }
            }
            __syncthreads();
        }
        #pragma unroll
        for (int m = 0; m < 4; m++) r[m] = sp[base + m];
        warp_merge(r, base, k, 64);
        #pragma unroll
        for (int m = 0; m < 4; m++) sp[base + m] = r[m];
        __syncthreads();
    }

    #pragma unroll
    for (int m = 0; m < 4; m++) g_runs[gbase + base + m] = sp[base + m];
}

// ---------------- K2b: global rank via binary search + scatter (grid = BB*NN/256) ------
__global__ __launch_bounds__(256) void k2b_rank()
{
    int gid = blockIdx.x * 256 + threadIdx.x;   // 0..BB*NN-1
    int b   = gid >> 12;
    int pos = gid & (NN-1);
    int run = pos >> 9;
    int loc = pos & (RUN-1);

    const unsigned long long* runs = g_runs + b*NN;
    unsigned long long pv = runs[pos];

    int rank = loc;
    #pragma unroll
    for (int r2 = 0; r2 < NRUN; r2++) {
        if (r2 == run) continue;
        const unsigned long long* R = runs + r2*RUN;
        int lo = 0, hi = RUN;
        #pragma unroll
        for (int s = 0; s < 10; s++) {         // interval 512 -> 0 needs 10 halvings
            if (lo < hi) {
                int mid = (lo + hi) >> 1;
                if (R[mid] < pv) lo = mid + 1; else hi = mid;
            }
        }
        rank += lo;
    }

    // M2 = max over the 8 run tails
    unsigned long long mx = runs[RUN-1];
    #pragma unroll
    for (int r2 = 1; r2 < NRUN; r2++) {
        unsigned long long t = runs[r2*RUN + RUN-1];
        if (t > mx) mx = t;
    }
    unsigned hiM = (unsigned)(mx >> 32);
    unsigned uM  = (hiM & 0x80000000u) ? (hiM ^ 0x80000000u) : ~hiM;
    float M2 = __uint_as_float(uM);
    if (pos == 0) g_M2[b] = M2;

    unsigned hk = (unsigned)(pv >> 32);
    unsigned uv = (hk & 0x80000000u) ? (hk ^ 0x80000000u) : ~hk;
    float v = __uint_as_float(uv);

    g_sval[b*NN + rank] = v;
    g_sidx[b*NN + rank] = (int)(pv & 0xffffffffu);
    g_E1[b*NN + rank] = __expf(v - M2);
    g_E2[b*NN + rank] = __expf(ALPHA * v);
}

// ---------------- K3a: chunk partial sums, one warp per chunk (grid = BB*G/8, block=256) ----
__global__ __launch_bounds__(256) void k3a_partial()
{
    int tid  = threadIdx.x;
    int wrp  = tid >> 5;                   // chunk in block (0..7)
    int lane = tid & 31;
    int half = lane >> 4;                  // 0/1
    int c4   = lane & 15;                  // float4 channel group
    int bg   = blockIdx.x * 8 + wrp;       // b*G + g
    int b    = bg >> 8;
    int g    = bg & (G-1);
    int base = g * CH + half * (CH/2);

    const float4* hB4  = (const float4*)g_h + (size_t)b*NN*16;
    const int*    sidx = g_sidx + b*NN;
    const float*  E1   = g_E1   + b*NN;
    const float*  E2   = g_E2   + b*NN;

    float4 aL = make_float4(0.f,0.f,0.f,0.f);
    float4 aG = make_float4(0.f,0.f,0.f,0.f);
    #pragma unroll
    for (int k = base; k < base + CH/2; k++) {
        float4 hv = hB4[(size_t)sidx[k]*16 + c4];
        float e2 = E2[k], e1 = E1[k];
        aL.x = fmaf(e2, hv.x, aL.x); aL.y = fmaf(e2, hv.y, aL.y);
        aL.z = fmaf(e2, hv.z, aL.z); aL.w = fmaf(e2, hv.w, aL.w);
        aG.x = fmaf(e1, hv.x, aG.x); aG.y = fmaf(e1, hv.y, aG.y);
        aG.z = fmaf(e1, hv.z, aG.z); aG.w = fmaf(e1, hv.w, aG.w);
    }
    // combine halves (lane and lane+16)
    aL.x += __shfl_down_sync(FULL, aL.x, 16);
    aL.y += __shfl_down_sync(FULL, aL.y, 16);
    aL.z += __shfl_down_sync(FULL, aL.z, 16);
    aL.w += __shfl_down_sync(FULL, aL.w, 16);
    aG.x += __shfl_down_sync(FULL, aG.x, 16);
    aG.y += __shfl_down_sync(FULL, aG.y, 16);
    aG.z += __shfl_down_sync(FULL, aG.z, 16);
    aG.w += __shfl_down_sync(FULL, aG.w, 16);
    if (half == 0) {
        ((float4*)g_pl)[(size_t)bg*16 + c4] = aL;
        ((float4*)g_pg)[(size_t)bg*16 + c4] = aG;
    }
}

// ---------------- K3b: warp-shuffle scans over G=256 chunk partials ----------------
__device__ __forceinline__ float4 warp_iscan4(float4 v, int lane)
{
    #pragma unroll
    for (int o = 1; o < 32; o <<= 1) {
        float ux = __shfl_up_sync(FULL, v.x, o);
        float uy = __shfl_up_sync(FULL, v.y, o);
        float uz = __shfl_up_sync(FULL, v.z, o);
        float uw = __shfl_up_sync(FULL, v.w, o);
        if (lane >= o) { v.x += ux; v.y += uy; v.z += uz; v.w += uw; }
    }
    return v;
}
__device__ __forceinline__ float warp_iscan1(float v, int lane)
{
    #pragma unroll
    for (int o = 1; o < 32; o <<= 1) {
        float u = __shfl_up_sync(FULL, v, o);
        if (lane >= o) v += u;
    }
    return v;
}

// grid = BB*17: 16 float4-channel-group blocks + 1 scalar block per batch. block=256.
// Offsets indexed with stride (G+1); entry G holds {prefix: total, suffix: 0}.
__global__ __launch_bounds__(256) void k3b_offsets()
{
    int bx = blockIdx.x;
    int b  = bx / 17;
    int cg = bx % 17;
    int t  = threadIdx.x;                 // 0..255 (one per chunk)
    int lane = t & 31, w = t >> 5;        // 8 warps

    __shared__ float4 ws4[8];

    if (cg < 16) {
        // prefix over pl
        float4 pl = ((const float4*)g_pl)[(size_t)(b*G + t)*16 + cg];
        float4 v = warp_iscan4(pl, lane);
        if (lane == 31) ws4[w] = v;
        __syncthreads();
        float4 off = make_float4(0.f,0.f,0.f,0.f);
        for (int i = 0; i < w; i++) {
            float4 s = ws4[i];
            off.x += s.x; off.y += s.y; off.z += s.z; off.w += s.w;
        }
        float4 ofL = make_float4(v.x+off.x-pl.x, v.y+off.y-pl.y,
                                 v.z+off.z-pl.z, v.w+off.w-pl.w);
        ((float4*)g_ofL)[(size_t)(b*(G+1) + t)*16 + cg] = ofL;
        if (t == G-1)   // inclusive total -> boundary entry G
            ((float4*)g_ofL)[(size_t)(b*(G+1) + G)*16 + cg] =
                make_float4(v.x+off.x, v.y+off.y, v.z+off.z, v.w+off.w);
        __syncthreads();

        // suffix over pg: scan reversed order
        int gr = G - 1 - t;
        float4 pg = ((const float4*)g_pg)[(size_t)(b*G + gr)*16 + cg];
        v = warp_iscan4(pg, lane);
        if (lane == 31) ws4[w] = v;
        __syncthreads();
        off = make_float4(0.f,0.f,0.f,0.f);
        for (int i = 0; i < w; i++) {
            float4 s = ws4[i];
            off.x += s.x; off.y += s.y; off.z += s.z; off.w += s.w;
        }
        float4 ofG = make_float4(v.x+off.x-pg.x, v.y+off.y-pg.y,
                                 v.z+off.z-pg.z, v.w+off.w-pg.w);
        ((float4*)g_ofG)[(size_t)(b*(G+1) + gr)*16 + cg] = ofG;
        if (t == 0)     // boundary entry G = 0
            ((float4*)g_ofG)[(size_t)(b*(G+1) + G)*16 + cg] = make_float4(0.f,0.f,0.f,0.f);
    } else {
        float* wss = (float*)ws4;
        const float4* E2v = (const float4*)(g_E2 + b*NN);
        const float4* E1v = (const float4*)(g_E1 + b*NN);

        // prefix of per-chunk E2 sums (chunk t)
        float pls = 0.f;
        #pragma unroll
        for (int m = 0; m < CH/4; m++) {
            float4 e2 = E2v[t*(CH/4) + m];
            pls += (e2.x + e2.y) + (e2.z + e2.w);
        }
        float v = warp_iscan1(pls, lane);
        if (lane == 31) wss[w] = v;
        __syncthreads();
        float off = 0.f;
        for (int i = 0; i < w; i++) off += wss[i];
        g_ofLs[b*(G+1) + t] = v + off - pls;
        if (t == G-1) g_ofLs[b*(G+1) + G] = v + off;
        __syncthreads();

        // suffix of per-chunk E1 sums (chunk gr)
        int gr = G - 1 - t;
        float pgs = 0.f;
        #pragma unroll
        for (int m = 0; m < CH/4; m++) {
            float4 e1 = E1v[gr*(CH/4) + m];
            pgs += (e1.x + e1.y) + (e1.z + e1.w);
        }
        v = warp_iscan1(pgs, lane);
        if (lane == 31) wss[w] = v;
        __syncthreads();
        off = 0.f;
        for (int i = 0; i < w; i++) off += wss[i];
        g_ofGs[b*(G+1) + gr] = v + off - pgs;
        if (t == 0) g_ofGs[b*(G+1) + G] = 0.f;
    }
}

// ---------------- K4: threshold lookup + in-chunk residual + combine ----------------
// One warp per output row; lane handles 2 channels (float2).
__global__ __launch_bounds__(256) void k4_out(float* __restrict__ out)
{
    int gw   = (blockIdx.x * blockDim.x + threadIdx.x) >> 5;
    int lane = threadIdx.x & 31;
    if (gw >= BB*NN) return;
    int b = gw >> 12;

    float s1v = g_s1[gw];
    float M2  = g_M2[b];
    float thr = -s1v;

    const float* sval = g_sval + b*NN;
    int lo = 0, hi = NN;
    while (lo < hi) {
        int mid = (lo + hi) >> 1;
        if (sval[mid] < thr) lo = mid + 1; else hi = mid;
    }
    int k = lo;
    int g = k >> 4;                      // chunk (CH=16); g == G possible when k == NN

    float x = s1v + M2;
    float m = (x >= 0.f) ? x : ALPHA * x;       // row max of lrelu logits
    float cge = __expf(x - m);                  // pairs with E1 = exp(s2 - M2)
    float clt = __expf(ALPHA * s1v - m);        // pairs with E2 = exp(alpha*s2)

    const float2* ofL2 = (const float2*)g_ofL + ((size_t)(b*(G+1) + g))*32;
    const float2* ofG2 = (const float2*)g_ofG + ((size_t)(b*(G+1) + g))*32;
    float2 lt = ofL2[lane];
    float2 ge = ofG2[lane];
    float dlt = g_ofLs[b*(G+1) + g];
    float dge = g_ofGs[b*(G+1) + g];

    if (g < G) {
        const int*    sidx = g_sidx + b*NN;
        const float*  E1   = g_E1   + b*NN;
        const float*  E2   = g_E2   + b*NN;
        const float2* h2   = (const float2*)g_h + (size_t)b*NN*32;
        int base = g * CH;
        #pragma unroll
        for (int j = base; j < base + CH; j++) {
            float2 hv = h2[(size_t)sidx[j]*32 + lane];
            if (j < k) {
                float e2 = E2[j];
                lt.x = fmaf(e2, hv.x, lt.x); lt.y = fmaf(e2, hv.y, lt.y);
                dlt += e2;
            } else {
                float e1 = E1[j];
                ge.x = fmaf(e1, hv.x, ge.x); ge.y = fmaf(e1, hv.y, ge.y);
                dge += e1;
            }
        }
    }

    float inv = 1.f / (cge * dge + clt * dlt);
    float o0 = (cge*ge.x + clt*lt.x) * inv;
    float o1 = (cge*ge.y + clt*lt.y) * inv;

    float2* op = (float2*)(out + (size_t)gw*64);
    op[lane] = make_float2(o0, o1);
}

// ---------------- launch ----------------
extern "C" void kernel_launch(void* const* d_in, const int* in_sizes, int n_in,
                              void* d_out, int out_size)
{
    const float* feat = (const float*)d_in[0];
    // d_in[1] = adj: unused by the reference computation — deliberately not read.
    const float* W    = (const float*)d_in[2];
    const float* a    = (const float*)d_in[3];
    float* out = (float*)d_out;

    k1_hsw<<<(BB*NN)/16, 256>>>(feat, W, a);
    k2a_sort_runs<<<BB*NRUN, 128>>>();
    k2b_rank<<<BB*NN/256, 256>>>();
    k3a_partial<<<BB*G/8, 256>>>();
    k3b_offsets<<<BB*17, 256>>>();
    k4_out<<<(BB*NN*32)/256, 256>>>(out);
}

// round 15
// speedup vs baseline: 1.4719x; 1.2149x over previous
#include <cuda_runtime.h>
#include <math.h>

#define BB 4
#define NN 4096
#define CC 64
#define ALPHA 0.2f
#define G  256          // scan chunks per batch
#define CH 16           // elements per chunk (NN = G*CH)
#define RUN 512         // sort run length
#define NRUN 8          // runs per batch
#define FULL 0xffffffffu

// ---------------- scratch (static device globals; no allocation) ----------------
__device__ __align__(16) float g_h[BB*NN*CC];        // h = feat @ W
__device__ __align__(16) float g_s1[BB*NN];
__device__ __align__(16) float g_s2[BB*NN];
__device__ float g_M2[BB];
__device__ __align__(16) float g_sval[BB*NN];        // sorted s2 (ascending) per batch
__device__ __align__(16) int   g_sidx[BB*NN];        // permutation
__device__ __align__(16) float g_E1[BB*NN];          // exp(sval - M2)
__device__ __align__(16) float g_E2[BB*NN];          // exp(alpha * sval)
__device__ __align__(16) unsigned long long g_runs[BB*NN]; // sorted runs (packed key|idx)
// scan intermediates — layout [b][c4-group][chunk] (transposed for coalesced k3b)
__device__ __align__(16) float g_pl [BB*16*G*4],     g_pg [BB*16*G*4];
__device__ __align__(16) float g_ofL[BB*16*(G+1)*4], g_ofG[BB*16*(G+1)*4];
__device__ float g_ofLs[BB*(G+1)], g_ofGs[BB*(G+1)];

// ---------------- K1: h = feat @ W, s1 = h.a1, s2 = h.a2 ----------------
// 64 rows per block; thread = (row-quad rq 0..15, channel-quad c4 0..15).
// Register blocking 4 rows x 4 channels: one float4 W load feeds 16 FMAs.
__global__ __launch_bounds__(256) void k1_hsw(const float* __restrict__ feat,
                                              const float* __restrict__ W,
                                              const float* __restrict__ a)
{
    __shared__ float4 Ws4[64*16];      // [k][c4]
    __shared__ float  fs[64][64];      // [local row][k]
    __shared__ float4 a14[16], a24[16];

    int tid = threadIdx.x;             // 256
    int c4  = tid & 15;
    int rq  = tid >> 4;                // 0..15
    int rowbase = blockIdx.x * 64;

    const float4* Wg = (const float4*)W;
    #pragma unroll
    for (int i = tid; i < 1024; i += 256) Ws4[i] = Wg[i];
    if (tid < 16) { a14[tid] = ((const float4*)a)[tid]; a24[tid] = ((const float4*)a)[16 + tid]; }
    const float4* fg = (const float4*)(feat + (size_t)rowbase*64);
    #pragma unroll
    for (int i = tid; i < 1024; i += 256) ((float4*)fs)[i] = fg[i];
    __syncthreads();

    float4 acc0 = make_float4(0.f,0.f,0.f,0.f);
    float4 acc1 = acc0, acc2 = acc0, acc3 = acc0;
    int r0 = rq * 4;

    #pragma unroll 8
    for (int k = 0; k < 64; k++) {
        float4 w = Ws4[k*16 + c4];
        float f0 = fs[r0+0][k], f1 = fs[r0+1][k], f2 = fs[r0+2][k], f3 = fs[r0+3][k];
        acc0.x = fmaf(f0, w.x, acc0.x); acc0.y = fmaf(f0, w.y, acc0.y);
        acc0.z = fmaf(f0, w.z, acc0.z); acc0.w = fmaf(f0, w.w, acc0.w);
        acc1.x = fmaf(f1, w.x, acc1.x); acc1.y = fmaf(f1, w.y, acc1.y);
        acc1.z = fmaf(f1, w.z, acc1.z); acc1.w = fmaf(f1, w.w, acc1.w);
        acc2.x = fmaf(f2, w.x, acc2.x); acc2.y = fmaf(f2, w.y, acc2.y);
        acc2.z = fmaf(f2, w.z, acc2.z); acc2.w = fmaf(f2, w.w, acc2.w);
        acc3.x = fmaf(f3, w.x, acc3.x); acc3.y = fmaf(f3, w.y, acc3.y);
        acc3.z = fmaf(f3, w.z, acc3.z); acc3.w = fmaf(f3, w.w, acc3.w);
    }

    float4* h4 = (float4*)g_h;
    h4[(size_t)(rowbase + r0 + 0)*16 + c4] = acc0;
    h4[(size_t)(rowbase + r0 + 1)*16 + c4] = acc1;
    h4[(size_t)(rowbase + r0 + 2)*16 + c4] = acc2;
    h4[(size_t)(rowbase + r0 + 3)*16 + c4] = acc3;

    float4 a1v = a14[c4], a2v = a24[c4];
    float p10 = acc0.x*a1v.x + acc0.y*a1v.y + acc0.z*a1v.z + acc0.w*a1v.w;
    float p11 = acc1.x*a1v.x + acc1.y*a1v.y + acc1.z*a1v.z + acc1.w*a1v.w;
    float p12 = acc2.x*a1v.x + acc2.y*a1v.y + acc2.z*a1v.z + acc2.w*a1v.w;
    float p13 = acc3.x*a1v.x + acc3.y*a1v.y + acc3.z*a1v.z + acc3.w*a1v.w;
    float p20 = acc0.x*a2v.x + acc0.y*a2v.y + acc0.z*a2v.z + acc0.w*a2v.w;
    float p21 = acc1.x*a2v.x + acc1.y*a2v.y + acc1.z*a2v.z + acc1.w*a2v.w;
    float p22 = acc2.x*a2v.x + acc2.y*a2v.y + acc2.z*a2v.z + acc2.w*a2v.w;
    float p23 = acc3.x*a2v.x + acc3.y*a2v.y + acc3.z*a2v.z + acc3.w*a2v.w;

    // reduce over the 16 c4-lanes (xor masks < 16 stay in the half-warp)
    #pragma unroll
    for (int o = 8; o >= 1; o >>= 1) {
        p10 += __shfl_xor_sync(FULL, p10, o); p11 += __shfl_xor_sync(FULL, p11, o);
        p12 += __shfl_xor_sync(FULL, p12, o); p13 += __shfl_xor_sync(FULL, p13, o);
        p20 += __shfl_xor_sync(FULL, p20, o); p21 += __shfl_xor_sync(FULL, p21, o);
        p22 += __shfl_xor_sync(FULL, p22, o); p23 += __shfl_xor_sync(FULL, p23, o);
    }
    if (c4 == 0) {
        int row = rowbase + r0;
        g_s1[row+0] = p10; g_s1[row+1] = p11; g_s1[row+2] = p12; g_s1[row+3] = p13;
        g_s2[row+0] = p20; g_s2[row+1] = p21; g_s2[row+2] = p22; g_s2[row+3] = p23;
    }
}

// ---------------- bitonic helpers (packed u64 key|idx) ----------------
__device__ __forceinline__ void cswap2(unsigned long long r[4], int m0, int m1, bool asc)
{
    unsigned long long a = r[m0], b = r[m1];
    bool sw = asc ? (a > b) : (a < b);
    if (sw) { r[m0] = b; r[m1] = a; }
}

__device__ __forceinline__ void warp_merge(unsigned long long r[4], int base, int k, int jstart)
{
    for (int j = jstart; j >= 4; j >>= 1) {
        int d = j >> 2;                       // lane distance
        #pragma unroll
        for (int m = 0; m < 4; m++) {
            unsigned long long pv = __shfl_xor_sync(FULL, r[m], d);
            int i = base + m;
            bool keepmin = (((i & k) == 0) == ((i & j) == 0));
            bool pless   = pv < r[m];
            r[m] = (keepmin == pless) ? pv : r[m];
        }
    }
    bool a = ((base & k) == 0);               // uniform per thread for k >= 4
    cswap2(r, 0, 2, a); cswap2(r, 1, 3, a);
    cswap2(r, 0, 1, a); cswap2(r, 2, 3, a);
}

// ---------------- K2a: sort 512-element runs (grid = BB*NRUN, block = 128) -------------
__global__ __launch_bounds__(128) void k2a_sort_runs()
{
    int blk = blockIdx.x;                 // 0..31
    int b   = blk >> 3;
    int run = blk & 7;
    int tid = threadIdx.x;                // 128
    int base = tid * 4;                   // position within run
    int gbase = b*NN + run*RUN;

    __shared__ unsigned long long sp[RUN];

    unsigned long long r[4];
    #pragma unroll
    for (int m = 0; m < 4; m++) {
        int i = base + m;
        unsigned u   = __float_as_uint(g_s2[gbase + i]);
        unsigned key = (u & 0x80000000u) ? ~u : (u | 0x80000000u);
        r[m] = ((unsigned long long)key << 32) | (unsigned)(run*RUN + i);
    }

    cswap2(r, 0, 1, true); cswap2(r, 2, 3, false);
    #pragma unroll
    for (int k = 4; k <= 128; k <<= 1)
        warp_merge(r, base, k, k >> 1);

    #pragma unroll
    for (int m = 0; m < 4; m++) sp[base + m] = r[m];
    __syncthreads();

    for (int k = 256; k <= RUN; k <<= 1) {
        for (int j = k >> 1; j >= 128; j >>= 1) {
            #pragma unroll
            for (int m = 0; m < 4; m++) {
                int i = base + m;
                int ixj = i ^ j;
                if (ixj > i) {
                    unsigned long long va = sp[i], vb = sp[ixj];
                    bool asc = ((i & k) == 0);
                    bool sw  = asc ? (va > vb) : (va < vb);
                    if (sw) { sp[i] = vb; sp[ixj] = va; }
                }
            }
            __syncthreads();
        }
        #pragma unroll
        for (int m = 0; m < 4; m++) r[m] = sp[base + m];
        warp_merge(r, base, k, 64);
        #pragma unroll
        for (int m = 0; m < 4; m++) sp[base + m] = r[m];
        __syncthreads();
    }

    #pragma unroll
    for (int m = 0; m < 4; m++) g_runs[gbase + base + m] = sp[base + m];
}

// ---------------- K2b: global rank via binary search + scatter (grid = BB*NN/256) ------
__global__ __launch_bounds__(256) void k2b_rank()
{
    int gid = blockIdx.x * 256 + threadIdx.x;   // 0..BB*NN-1
    int b   = gid >> 12;
    int pos = gid & (NN-1);
    int run = pos >> 9;
    int loc = pos & (RUN-1);

    const unsigned long long* runs = g_runs + b*NN;
    unsigned long long pv = runs[pos];

    int rank = loc;
    #pragma unroll
    for (int r2 = 0; r2 < NRUN; r2++) {
        if (r2 == run) continue;
        const unsigned long long* R = runs + r2*RUN;
        int lo = 0, hi = RUN;
        #pragma unroll
        for (int s = 0; s < 10; s++) {         // interval 512 -> 0 needs 10 halvings
            if (lo < hi) {
                int mid = (lo + hi) >> 1;
                if (R[mid] < pv) lo = mid + 1; else hi = mid;
            }
        }
        rank += lo;
    }

    // M2 = max over the 8 run tails
    unsigned long long mx = runs[RUN-1];
    #pragma unroll
    for (int r2 = 1; r2 < NRUN; r2++) {
        unsigned long long t = runs[r2*RUN + RUN-1];
        if (t > mx) mx = t;
    }
    unsigned hiM = (unsigned)(mx >> 32);
    unsigned uM  = (hiM & 0x80000000u) ? (hiM ^ 0x80000000u) : ~hiM;
    float M2 = __uint_as_float(uM);
    if (pos == 0) g_M2[b] = M2;

    unsigned hk = (unsigned)(pv >> 32);
    unsigned uv = (hk & 0x80000000u) ? (hk ^ 0x80000000u) : ~hk;
    float v = __uint_as_float(uv);

    g_sval[b*NN + rank] = v;
    g_sidx[b*NN + rank] = (int)(pv & 0xffffffffu);
    g_E1[b*NN + rank] = __expf(v - M2);
    g_E2[b*NN + rank] = __expf(ALPHA * v);
}

// ---------------- K3a: chunk partial sums, one warp per chunk (grid = BB*G/8, block=256) ----
__global__ __launch_bounds__(256) void k3a_partial()
{
    int tid  = threadIdx.x;
    int wrp  = tid >> 5;                   // chunk in block (0..7)
    int lane = tid & 31;
    int half = lane >> 4;                  // 0/1
    int c4   = lane & 15;                  // float4 channel group
    int bg   = blockIdx.x * 8 + wrp;       // b*G + g
    int b    = bg >> 8;
    int g    = bg & (G-1);
    int base = g * CH + half * (CH/2);

    const float4* hB4  = (const float4*)g_h + (size_t)b*NN*16;
    const int*    sidx = g_sidx + b*NN;
    const float*  E1   = g_E1   + b*NN;
    const float*  E2   = g_E2   + b*NN;

    float4 aL = make_float4(0.f,0.f,0.f,0.f);
    float4 aG = make_float4(0.f,0.f,0.f,0.f);
    #pragma unroll
    for (int k = base; k < base + CH/2; k++) {
        float4 hv = hB4[(size_t)sidx[k]*16 + c4];
        float e2 = E2[k], e1 = E1[k];
        aL.x = fmaf(e2, hv.x, aL.x); aL.y = fmaf(e2, hv.y, aL.y);
        aL.z = fmaf(e2, hv.z, aL.z); aL.w = fmaf(e2, hv.w, aL.w);
        aG.x = fmaf(e1, hv.x, aG.x); aG.y = fmaf(e1, hv.y, aG.y);
        aG.z = fmaf(e1, hv.z, aG.z); aG.w = fmaf(e1, hv.w, aG.w);
    }
    aL.x += __shfl_down_sync(FULL, aL.x, 16);
    aL.y += __shfl_down_sync(FULL, aL.y, 16);
    aL.z += __shfl_down_sync(FULL, aL.z, 16);
    aL.w += __shfl_down_sync(FULL, aL.w, 16);
    aG.x += __shfl_down_sync(FULL, aG.x, 16);
    aG.y += __shfl_down_sync(FULL, aG.y, 16);
    aG.z += __shfl_down_sync(FULL, aG.z, 16);
    aG.w += __shfl_down_sync(FULL, aG.w, 16);
    if (half == 0) {
        // transposed layout: [b][c4][g]
        ((float4*)g_pl)[(size_t)(b*16 + c4)*G + g] = aL;
        ((float4*)g_pg)[(size_t)(b*16 + c4)*G + g] = aG;
    }
}

// ---------------- K3b: warp-shuffle scans over G=256 chunk partials ----------------
__device__ __forceinline__ float4 warp_iscan4(float4 v, int lane)
{
    #pragma unroll
    for (int o = 1; o < 32; o <<= 1) {
        float ux = __shfl_up_sync(FULL, v.x, o);
        float uy = __shfl_up_sync(FULL, v.y, o);
        float uz = __shfl_up_sync(FULL, v.z, o);
        float uw = __shfl_up_sync(FULL, v.w, o);
        if (lane >= o) { v.x += ux; v.y += uy; v.z += uz; v.w += uw; }
    }
    return v;
}
__device__ __forceinline__ float warp_iscan1(float v, int lane)
{
    #pragma unroll
    for (int o = 1; o < 32; o <<= 1) {
        float u = __shfl_up_sync(FULL, v, o);
        if (lane >= o) v += u;
    }
    return v;
}

// grid = BB*17: 16 c4-group blocks + 1 scalar block per batch. block=256.
// Partials/offsets in [b][cg][chunk] layout -> fully coalesced here.
__global__ __launch_bounds__(256) void k3b_offsets()
{
    int bx = blockIdx.x;
    int b  = bx / 17;
    int cg = bx % 17;
    int t  = threadIdx.x;                 // 0..255 (one per chunk)
    int lane = t & 31, w = t >> 5;        // 8 warps

    __shared__ float4 ws4[8];

    if (cg < 16) {
        const float4* pl4 = (const float4*)g_pl + (size_t)(b*16 + cg)*G;
        const float4* pg4 = (const float4*)g_pg + (size_t)(b*16 + cg)*G;
        float4* ofL4 = (float4*)g_ofL + (size_t)(b*16 + cg)*(G+1);
        float4* ofG4 = (float4*)g_ofG + (size_t)(b*16 + cg)*(G+1);

        // prefix over pl
        float4 pl = pl4[t];
        float4 v = warp_iscan4(pl, lane);
        if (lane == 31) ws4[w] = v;
        __syncthreads();
        float4 off = make_float4(0.f,0.f,0.f,0.f);
        for (int i = 0; i < w; i++) {
            float4 s = ws4[i];
            off.x += s.x; off.y += s.y; off.z += s.z; off.w += s.w;
        }
        ofL4[t] = make_float4(v.x+off.x-pl.x, v.y+off.y-pl.y,
                              v.z+off.z-pl.z, v.w+off.w-pl.w);
        if (t == G-1)
            ofL4[G] = make_float4(v.x+off.x, v.y+off.y, v.z+off.z, v.w+off.w);
        __syncthreads();

        // suffix over pg: scan reversed order
        int gr = G - 1 - t;
        float4 pg = pg4[gr];
        v = warp_iscan4(pg, lane);
        if (lane == 31) ws4[w] = v;
        __syncthreads();
        off = make_float4(0.f,0.f,0.f,0.f);
        for (int i = 0; i < w; i++) {
            float4 s = ws4[i];
            off.x += s.x; off.y += s.y; off.z += s.z; off.w += s.w;
        }
        ofG4[gr] = make_float4(v.x+off.x-pg.x, v.y+off.y-pg.y,
                               v.z+off.z-pg.z, v.w+off.w-pg.w);
        if (t == 0) ofG4[G] = make_float4(0.f,0.f,0.f,0.f);
    } else {
        float* wss = (float*)ws4;
        const float4* E2v = (const float4*)(g_E2 + b*NN);
        const float4* E1v = (const float4*)(g_E1 + b*NN);

        float pls = 0.f;
        #pragma unroll
        for (int m = 0; m < CH/4; m++) {
            float4 e2 = E2v[t*(CH/4) + m];
            pls += (e2.x + e2.y) + (e2.z + e2.w);
        }
        float v = warp_iscan1(pls, lane);
        if (lane == 31) wss[w] = v;
        __syncthreads();
        float off = 0.f;
        for (int i = 0; i < w; i++) off += wss[i];
        g_ofLs[b*(G+1) + t] = v + off - pls;
        if (t == G-1) g_ofLs[b*(G+1) + G] = v + off;
        __syncthreads();

        int gr = G - 1 - t;
        float pgs = 0.f;
        #pragma unroll
        for (int m = 0; m < CH/4; m++) {
            float4 e1 = E1v[gr*(CH/4) + m];
            pgs += (e1.x + e1.y) + (e1.z + e1.w);
        }
        v = warp_iscan1(pgs, lane);
        if (lane == 31) wss[w] = v;
        __syncthreads();
        off = 0.f;
        for (int i = 0; i < w; i++) off += wss[i];
        g_ofGs[b*(G+1) + gr] = v + off - pgs;
        if (t == 0) g_ofGs[b*(G+1) + G] = 0.f;
    }
}

// ---------------- K4: threshold lookup + in-chunk residual + combine ----------------
// One warp per output row; lane handles 2 channels (float2).
__global__ __launch_bounds__(256) void k4_out(float* __restrict__ out)
{
    int gw   = (blockIdx.x * blockDim.x + threadIdx.x) >> 5;
    int lane = threadIdx.x & 31;
    if (gw >= BB*NN) return;
    int b = gw >> 12;

    float s1v = g_s1[gw];
    float M2  = g_M2[b];
    float thr = -s1v;

    const float* sval = g_sval + b*NN;
    int lo = 0, hi = NN;
    while (lo < hi) {
        int mid = (lo + hi) >> 1;
        if (sval[mid] < thr) lo = mid + 1; else hi = mid;
    }
    int k = lo;
    int g = k >> 4;                      // chunk (CH=16); g == G possible when k == NN

    float x = s1v + M2;
    float m = (x >= 0.f) ? x : ALPHA * x;       // row max of lrelu logits
    float cge = __expf(x - m);                  // pairs with E1 = exp(s2 - M2)
    float clt = __expf(ALPHA * s1v - m);        // pairs with E2 = exp(alpha*s2)

    // offsets in [b][c4][chunk] layout; lane -> (c4 = lane>>1, part = lane&1)
    int c4 = lane >> 1, part = lane & 1;
    const float2* ofL2 = (const float2*)g_ofL;
    const float2* ofG2 = (const float2*)g_ofG;
    size_t oidx = ((size_t)(b*16 + c4)*(G+1) + g)*2 + part;
    float2 lt = ofL2[oidx];
    float2 ge = ofG2[oidx];
    float dlt = g_ofLs[b*(G+1) + g];
    float dge = g_ofGs[b*(G+1) + g];

    if (g < G) {
        const int*    sidx = g_sidx + b*NN;
        const float*  E1   = g_E1   + b*NN;
        const float*  E2   = g_E2   + b*NN;
        const float2* h2   = (const float2*)g_h + (size_t)b*NN*32;
        int base = g * CH;
        #pragma unroll
        for (int j = base; j < base + CH; j++) {
            float2 hv = h2[(size_t)sidx[j]*32 + lane];
            if (j < k) {
                float e2 = E2[j];
                lt.x = fmaf(e2, hv.x, lt.x); lt.y = fmaf(e2, hv.y, lt.y);
                dlt += e2;
            } else {
                float e1 = E1[j];
                ge.x = fmaf(e1, hv.x, ge.x); ge.y = fmaf(e1, hv.y, ge.y);
                dge += e1;
            }
        }
    }

    float inv = 1.f / (cge * dge + clt * dlt);
    float o0 = (cge*ge.x + clt*lt.x) * inv;
    float o1 = (cge*ge.y + clt*lt.y) * inv;

    float2* op = (float2*)(out + (size_t)gw*64);
    op[lane] = make_float2(o0, o1);
}

// ---------------- launch ----------------
extern "C" void kernel_launch(void* const* d_in, const int* in_sizes, int n_in,
                              void* d_out, int out_size)
{
    const float* feat = (const float*)d_in[0];
    // d_in[1] = adj: unused by the reference computation — deliberately not read.
    const float* W    = (const float*)d_in[2];
    const float* a    = (const float*)d_in[3];
    float* out = (float*)d_out;

    k1_hsw<<<(BB*NN)/64, 256>>>(feat, W, a);
    k2a_sort_runs<<<BB*NRUN, 128>>>();
    k2b_rank<<<BB*NN/256, 256>>>();
    k3a_partial<<<BB*G/8, 256>>>();
    k3b_offsets<<<BB*17, 256>>>();
    k4_out<<<(BB*NN*32)/256, 256>>>(out);
}

// round 17
// speedup vs baseline: 1.5356x; 1.0433x over previous
#include <cuda_runtime.h>
#include <math.h>

#define BB 4
#define NN 4096
#define CC 64
#define ALPHA 0.2f
#define G  256          // scan chunks per batch
#define CH 16           // elements per chunk (NN = G*CH)
#define RUN 512         // sort run length
#define NRUN 8          // runs per batch
#define FULL 0xffffffffu

// ---------------- scratch (static device globals; no allocation) ----------------
__device__ __align__(16) float g_h[BB*NN*CC];        // h = feat @ W
__device__ __align__(16) float g_s1[BB*NN];
__device__ __align__(16) float g_s2[BB*NN];
__device__ float g_M2[BB];
__device__ __align__(16) float g_sval[BB*NN];        // sorted s2 (ascending) per batch
__device__ __align__(16) int   g_sidx[BB*NN];        // permutation
__device__ __align__(16) float g_E1[BB*NN];          // exp(sval - M2)
__device__ __align__(16) float g_E2[BB*NN];          // exp(alpha * sval)
__device__ __align__(16) unsigned long long g_runs[BB*NN]; // sorted runs (packed key|idx)
// scan intermediates — layout [b][c4-group][chunk] (transposed for coalesced k3b)
__device__ __align__(16) float g_pl [BB*16*G*4],     g_pg [BB*16*G*4];
__device__ __align__(16) float g_ofL[BB*16*(G+1)*4], g_ofG[BB*16*(G+1)*4];
__device__ float g_ofLs[BB*(G+1)], g_ofGs[BB*(G+1)];

// ---------------- K1: h = feat @ W, s1 = h.a1, s2 = h.a2 ----------------
// 64 rows per block; thread = (row-quad rq 0..15, channel-quad c4 0..15).
__global__ __launch_bounds__(256) void k1_hsw(const float* __restrict__ feat,
                                              const float* __restrict__ W,
                                              const float* __restrict__ a)
{
    __shared__ float4 Ws4[64*16];      // [k][c4]
    __shared__ float  fs[64][64];      // [local row][k]
    __shared__ float4 a14[16], a24[16];

    int tid = threadIdx.x;             // 256
    int c4  = tid & 15;
    int rq  = tid >> 4;                // 0..15
    int rowbase = blockIdx.x * 64;

    const float4* Wg = (const float4*)W;
    #pragma unroll
    for (int i = tid; i < 1024; i += 256) Ws4[i] = Wg[i];
    if (tid < 16) { a14[tid] = ((const float4*)a)[tid]; a24[tid] = ((const float4*)a)[16 + tid]; }
    const float4* fg = (const float4*)(feat + (size_t)rowbase*64);
    #pragma unroll
    for (int i = tid; i < 1024; i += 256) ((float4*)fs)[i] = fg[i];
    __syncthreads();

    float4 acc0 = make_float4(0.f,0.f,0.f,0.f);
    float4 acc1 = acc0, acc2 = acc0, acc3 = acc0;
    int r0 = rq * 4;

    #pragma unroll 8
    for (int k = 0; k < 64; k++) {
        float4 w = Ws4[k*16 + c4];
        float f0 = fs[r0+0][k], f1 = fs[r0+1][k], f2 = fs[r0+2][k], f3 = fs[r0+3][k];
        acc0.x = fmaf(f0, w.x, acc0.x); acc0.y = fmaf(f0, w.y, acc0.y);
        acc0.z = fmaf(f0, w.z, acc0.z); acc0.w = fmaf(f0, w.w, acc0.w);
        acc1.x = fmaf(f1, w.x, acc1.x); acc1.y = fmaf(f1, w.y, acc1.y);
        acc1.z = fmaf(f1, w.z, acc1.z); acc1.w = fmaf(f1, w.w, acc1.w);
        acc2.x = fmaf(f2, w.x, acc2.x); acc2.y = fmaf(f2, w.y, acc2.y);
        acc2.z = fmaf(f2, w.z, acc2.z); acc2.w = fmaf(f2, w.w, acc2.w);
        acc3.x = fmaf(f3, w.x, acc3.x); acc3.y = fmaf(f3, w.y, acc3.y);
        acc3.z = fmaf(f3, w.z, acc3.z); acc3.w = fmaf(f3, w.w, acc3.w);
    }

    float4* h4 = (float4*)g_h;
    h4[(size_t)(rowbase + r0 + 0)*16 + c4] = acc0;
    h4[(size_t)(rowbase + r0 + 1)*16 + c4] = acc1;
    h4[(size_t)(rowbase + r0 + 2)*16 + c4] = acc2;
    h4[(size_t)(rowbase + r0 + 3)*16 + c4] = acc3;

    float4 a1v = a14[c4], a2v = a24[c4];
    float p10 = acc0.x*a1v.x + acc0.y*a1v.y + acc0.z*a1v.z + acc0.w*a1v.w;
    float p11 = acc1.x*a1v.x + acc1.y*a1v.y + acc1.z*a1v.z + acc1.w*a1v.w;
    float p12 = acc2.x*a1v.x + acc2.y*a1v.y + acc2.z*a1v.z + acc2.w*a1v.w;
    float p13 = acc3.x*a1v.x + acc3.y*a1v.y + acc3.z*a1v.z + acc3.w*a1v.w;
    float p20 = acc0.x*a2v.x + acc0.y*a2v.y + acc0.z*a2v.z + acc0.w*a2v.w;
    float p21 = acc1.x*a2v.x + acc1.y*a2v.y + acc1.z*a2v.z + acc1.w*a2v.w;
    float p22 = acc2.x*a2v.x + acc2.y*a2v.y + acc2.z*a2v.z + acc2.w*a2v.w;
    float p23 = acc3.x*a2v.x + acc3.y*a2v.y + acc3.z*a2v.z + acc3.w*a2v.w;

    #pragma unroll
    for (int o = 8; o >= 1; o >>= 1) {
        p10 += __shfl_xor_sync(FULL, p10, o); p11 += __shfl_xor_sync(FULL, p11, o);
        p12 += __shfl_xor_sync(FULL, p12, o); p13 += __shfl_xor_sync(FULL, p13, o);
        p20 += __shfl_xor_sync(FULL, p20, o); p21 += __shfl_xor_sync(FULL, p21, o);
        p22 += __shfl_xor_sync(FULL, p22, o); p23 += __shfl_xor_sync(FULL, p23, o);
    }
    if (c4 == 0) {
        int row = rowbase + r0;
        g_s1[row+0] = p10; g_s1[row+1] = p11; g_s1[row+2] = p12; g_s1[row+3] = p13;
        g_s2[row+0] = p20; g_s2[row+1] = p21; g_s2[row+2] = p22; g_s2[row+3] = p23;
    }
}

// ---------------- bitonic helpers (packed u64 key|idx) ----------------
__device__ __forceinline__ void cswap2(unsigned long long r[4], int m0, int m1, bool asc)
{
    unsigned long long a = r[m0], b = r[m1];
    bool sw = asc ? (a > b) : (a < b);
    if (sw) { r[m0] = b; r[m1] = a; }
}

__device__ __forceinline__ void warp_merge(unsigned long long r[4], int base, int k, int jstart)
{
    for (int j = jstart; j >= 4; j >>= 1) {
        int d = j >> 2;                       // lane distance
        #pragma unroll
        for (int m = 0; m < 4; m++) {
            unsigned long long pv = __shfl_xor_sync(FULL, r[m], d);
            int i = base + m;
            bool keepmin = (((i & k) == 0) == ((i & j) == 0));
            bool pless   = pv < r[m];
            r[m] = (keepmin == pless) ? pv : r[m];
        }
    }
    bool a = ((base & k) == 0);               // uniform per thread for k >= 4
    cswap2(r, 0, 2, a); cswap2(r, 1, 3, a);
    cswap2(r, 0, 1, a); cswap2(r, 2, 3, a);
}

// ---------------- K2a: sort 512-element runs (grid = BB*NRUN, block = 128) -------------
__global__ __launch_bounds__(128) void k2a_sort_runs()
{
    int blk = blockIdx.x;                 // 0..31
    int b   = blk >> 3;
    int run = blk & 7;
    int tid = threadIdx.x;                // 128
    int base = tid * 4;                   // position within run
    int gbase = b*NN + run*RUN;

    __shared__ unsigned long long sp[RUN];

    unsigned long long r[4];
    #pragma unroll
    for (int m = 0; m < 4; m++) {
        int i = base + m;
        unsigned u   = __float_as_uint(g_s2[gbase + i]);
        unsigned key = (u & 0x80000000u) ? ~u : (u | 0x80000000u);
        r[m] = ((unsigned long long)key << 32) | (unsigned)(run*RUN + i);
    }

    cswap2(r, 0, 1, true); cswap2(r, 2, 3, false);
    #pragma unroll
    for (int k = 4; k <= 128; k <<= 1)
        warp_merge(r, base, k, k >> 1);

    #pragma unroll
    for (int m = 0; m < 4; m++) sp[base + m] = r[m];
    __syncthreads();

    for (int k = 256; k <= RUN; k <<= 1) {
        for (int j = k >> 1; j >= 128; j >>= 1) {
            #pragma unroll
            for (int m = 0; m < 4; m++) {
                int i = base + m;
                int ixj = i ^ j;
                if (ixj > i) {
                    unsigned long long va = sp[i], vb = sp[ixj];
                    bool asc = ((i & k) == 0);
                    bool sw  = asc ? (va > vb) : (va < vb);
                    if (sw) { sp[i] = vb; sp[ixj] = va; }
                }
            }
            __syncthreads();
        }
        #pragma unroll
        for (int m = 0; m < 4; m++) r[m] = sp[base + m];
        warp_merge(r, base, k, 64);
        #pragma unroll
        for (int m = 0; m < 4; m++) sp[base + m] = r[m];
        __syncthreads();
    }

    #pragma unroll
    for (int m = 0; m < 4; m++) g_runs[gbase + base + m] = sp[base + m];
}

// ---------------- K2b: global rank via binary search + scatter (grid = BB*NN/256) ------
__global__ __launch_bounds__(256) void k2b_rank()
{
    int gid = blockIdx.x * 256 + threadIdx.x;   // 0..BB*NN-1
    int b   = gid >> 12;
    int pos = gid & (NN-1);
    int run = pos >> 9;
    int loc = pos & (RUN-1);

    const unsigned long long* runs = g_runs + b*NN;
    unsigned long long pv = runs[pos];

    int rank = loc;
    #pragma unroll
    for (int r2 = 0; r2 < NRUN; r2++) {
        if (r2 == run) continue;
        const unsigned long long* R = runs + r2*RUN;
        int lo = 0, hi = RUN;
        #pragma unroll
        for (int s = 0; s < 10; s++) {         // interval 512 -> 0 needs 10 halvings
            if (lo < hi) {
                int mid = (lo + hi) >> 1;
                if (R[mid] < pv) lo = mid + 1; else hi = mid;
            }
        }
        rank += lo;
    }

    // M2 = max over the 8 run tails
    unsigned long long mx = runs[RUN-1];
    #pragma unroll
    for (int r2 = 1; r2 < NRUN; r2++) {
        unsigned long long t = runs[r2*RUN + RUN-1];
        if (t > mx) mx = t;
    }
    unsigned hiM = (unsigned)(mx >> 32);
    unsigned uM  = (hiM & 0x80000000u) ? (hiM ^ 0x80000000u) : ~hiM;
    float M2 = __uint_as_float(uM);
    if (pos == 0) g_M2[b] = M2;

    unsigned hk = (unsigned)(pv >> 32);
    unsigned uv = (hk & 0x80000000u) ? (hk ^ 0x80000000u) : ~hk;
    float v = __uint_as_float(uv);

    g_sval[b*NN + rank] = v;
    g_sidx[b*NN + rank] = (int)(pv & 0xffffffffu);
    g_E1[b*NN + rank] = __expf(v - M2);
    g_E2[b*NN + rank] = __expf(ALPHA * v);
}

// ---------------- K3a: chunk partial sums, one warp per chunk (grid = BB*G/4, block=128) ----
__global__ __launch_bounds__(128) void k3a_partial()
{
    int tid  = threadIdx.x;
    int wrp  = tid >> 5;                   // chunk in block (0..3)
    int lane = tid & 31;
    int half = lane >> 4;                  // 0/1
    int c4   = lane & 15;                  // float4 channel group
    int bg   = blockIdx.x * 4 + wrp;       // b*G + g
    int b    = bg >> 8;
    int g    = bg & (G-1);
    int base = g * CH + half * (CH/2);

    const float4* hB4  = (const float4*)g_h + (size_t)b*NN*16;
    const int*    sidx = g_sidx + b*NN;
    const float*  E1   = g_E1   + b*NN;
    const float*  E2   = g_E2   + b*NN;

    float4 aL = make_float4(0.f,0.f,0.f,0.f);
    float4 aG = make_float4(0.f,0.f,0.f,0.f);
    #pragma unroll
    for (int k = base; k < base + CH/2; k++) {
        float4 hv = hB4[(size_t)sidx[k]*16 + c4];
        float e2 = E2[k], e1 = E1[k];
        aL.x = fmaf(e2, hv.x, aL.x); aL.y = fmaf(e2, hv.y, aL.y);
        aL.z = fmaf(e2, hv.z, aL.z); aL.w = fmaf(e2, hv.w, aL.w);
        aG.x = fmaf(e1, hv.x, aG.x); aG.y = fmaf(e1, hv.y, aG.y);
        aG.z = fmaf(e1, hv.z, aG.z); aG.w = fmaf(e1, hv.w, aG.w);
    }
    aL.x += __shfl_down_sync(FULL, aL.x, 16);
    aL.y += __shfl_down_sync(FULL, aL.y, 16);
    aL.z += __shfl_down_sync(FULL, aL.z, 16);
    aL.w += __shfl_down_sync(FULL, aL.w, 16);
    aG.x += __shfl_down_sync(FULL, aG.x, 16);
    aG.y += __shfl_down_sync(FULL, aG.y, 16);
    aG.z += __shfl_down_sync(FULL, aG.z, 16);
    aG.w += __shfl_down_sync(FULL, aG.w, 16);
    if (half == 0) {
        // transposed layout: [b][c4][g]
        ((float4*)g_pl)[(size_t)(b*16 + c4)*G + g] = aL;
        ((float4*)g_pg)[(size_t)(b*16 + c4)*G + g] = aG;
    }
}

// ---------------- K3b: warp-shuffle scans over G=256 chunk partials ----------------
__device__ __forceinline__ float4 warp_iscan4(float4 v, int lane)
{
    #pragma unroll
    for (int o = 1; o < 32; o <<= 1) {
        float ux = __shfl_up_sync(FULL, v.x, o);
        float uy = __shfl_up_sync(FULL, v.y, o);
        float uz = __shfl_up_sync(FULL, v.z, o);
        float uw = __shfl_up_sync(FULL, v.w, o);
        if (lane >= o) { v.x += ux; v.y += uy; v.z += uz; v.w += uw; }
    }
    return v;
}
__device__ __forceinline__ float warp_iscan1(float v, int lane)
{
    #pragma unroll
    for (int o = 1; o < 32; o <<= 1) {
        float u = __shfl_up_sync(FULL, v, o);
        if (lane >= o) v += u;
    }
    return v;
}

// grid = BB*17: 16 c4-group blocks + 1 scalar block per batch. block=256.
__global__ __launch_bounds__(256) void k3b_offsets()
{
    int bx = blockIdx.x;
    int b  = bx / 17;
    int cg = bx % 17;
    int t  = threadIdx.x;                 // 0..255 (one per chunk)
    int lane = t & 31, w = t >> 5;        // 8 warps

    __shared__ float4 ws4[8];

    if (cg < 16) {
        const float4* pl4 = (const float4*)g_pl + (size_t)(b*16 + cg)*G;
        const float4* pg4 = (const float4*)g_pg + (size_t)(b*16 + cg)*G;
        float4* ofL4 = (float4*)g_ofL + (size_t)(b*16 + cg)*(G+1);
        float4* ofG4 = (float4*)g_ofG + (size_t)(b*16 + cg)*(G+1);

        // prefix over pl
        float4 pl = pl4[t];
        float4 v = warp_iscan4(pl, lane);
        if (lane == 31) ws4[w] = v;
        __syncthreads();
        float4 off = make_float4(0.f,0.f,0.f,0.f);
        for (int i = 0; i < w; i++) {
            float4 s = ws4[i];
            off.x += s.x; off.y += s.y; off.z += s.z; off.w += s.w;
        }
        ofL4[t] = make_float4(v.x+off.x-pl.x, v.y+off.y-pl.y,
                              v.z+off.z-pl.z, v.w+off.w-pl.w);
        if (t == G-1)
            ofL4[G] = make_float4(v.x+off.x, v.y+off.y, v.z+off.z, v.w+off.w);
        __syncthreads();

        // suffix over pg: scan reversed order
        int gr = G - 1 - t;
        float4 pg = pg4[gr];
        v = warp_iscan4(pg, lane);
        if (lane == 31) ws4[w] = v;
        __syncthreads();
        off = make_float4(0.f,0.f,0.f,0.f);
        for (int i = 0; i < w; i++) {
            float4 s = ws4[i];
            off.x += s.x; off.y += s.y; off.z += s.z; off.w += s.w;
        }
        ofG4[gr] = make_float4(v.x+off.x-pg.x, v.y+off.y-pg.y,
                               v.z+off.z-pg.z, v.w+off.w-pg.w);
        if (t == 0) ofG4[G] = make_float4(0.f,0.f,0.f,0.f);
    } else {
        float* wss = (float*)ws4;
        const float4* E2v = (const float4*)(g_E2 + b*NN);
        const float4* E1v = (const float4*)(g_E1 + b*NN);

        float pls = 0.f;
        #pragma unroll
        for (int m = 0; m < CH/4; m++) {
            float4 e2 = E2v[t*(CH/4) + m];
            pls += (e2.x + e2.y) + (e2.z + e2.w);
        }
        float v = warp_iscan1(pls, lane);
        if (lane == 31) wss[w] = v;
        __syncthreads();
        float off = 0.f;
        for (int i = 0; i < w; i++) off += wss[i];
        g_ofLs[b*(G+1) + t] = v + off - pls;
        if (t == G-1) g_ofLs[b*(G+1) + G] = v + off;
        __syncthreads();

        int gr = G - 1 - t;
        float pgs = 0.f;
        #pragma unroll
        for (int m = 0; m < CH/4; m++) {
            float4 e1 = E1v[gr*(CH/4) + m];
            pgs += (e1.x + e1.y) + (e1.z + e1.w);
        }
        v = warp_iscan1(pgs, lane);
        if (lane == 31) wss[w] = v;
        __syncthreads();
        off = 0.f;
        for (int i = 0; i < w; i++) off += wss[i];
        g_ofGs[b*(G+1) + gr] = v + off - pgs;
        if (t == 0) g_ofGs[b*(G+1) + G] = 0.f;
    }
}

// ---------------- K4: warp-parallel lower_bound + in-chunk residual + combine ----------
// One warp per output row; lane handles 2 channels (float2).
__global__ __launch_bounds__(256) void k4_out(float* __restrict__ out)
{
    int gw   = (blockIdx.x * blockDim.x + threadIdx.x) >> 5;
    int lane = threadIdx.x & 31;
    if (gw >= BB*NN) return;
    int b = gw >> 12;

    float s1v = g_s1[gw];
    float M2  = g_M2[b];
    float thr = -s1v;

    // warp-parallel lower_bound: 3 ballot rounds (step 128, 4, 1).
    // Invariant: indices < lo have sval < thr; indices >= hi have sval >= thr.
    const float* sval = g_sval + b*NN;
    int lo = 0, hi = NN;
    {
        int idx = lane << 7;                              // step 128, idx < NN
        bool pred = sval[idx] < thr;
        unsigned bal = __ballot_sync(FULL, pred);
        int n = __popc(bal);
        int nlo = (n > 0) ? ((n-1) << 7) + 1 : 0;
        if (n < 32) hi = n << 7;
        lo = nlo;
    }
    {
        int idx = lo + (lane << 2);                       // step 4, width <= 127
        bool pred = (idx < hi) && (sval[idx] < thr);
        unsigned bal = __ballot_sync(FULL, pred);
        int n = __popc(bal);
        int nlo = (n > 0) ? lo + ((n-1) << 2) + 1 : lo;
        hi = min(hi, lo + (n << 2));
        lo = nlo;
    }
    {
        int idx = lo + lane;                              // step 1, width <= 3
        bool pred = (idx < hi) && (sval[idx] < thr);
        unsigned bal = __ballot_sync(FULL, pred);
        lo += __popc(bal);
    }
    int k = lo;
    int g = k >> 4;                      // chunk (CH=16); g == G possible when k == NN

    float x = s1v + M2;
    float m = (x >= 0.f) ? x : ALPHA * x;       // row max of lrelu logits
    float cge = __expf(x - m);                  // pairs with E1 = exp(s2 - M2)
    float clt = __expf(ALPHA * s1v - m);        // pairs with E2 = exp(alpha*s2)

    // offsets in [b][c4][chunk] layout; lane -> (c4 = lane>>1, part = lane&1)
    int c4 = lane >> 1, part = lane & 1;
    const float2* ofL2 = (const float2*)g_ofL;
    const float2* ofG2 = (const float2*)g_ofG;
    size_t oidx = ((size_t)(b*16 + c4)*(G+1) + g)*2 + part;
    float2 lt = ofL2[oidx];
    float2 ge = ofG2[oidx];
    float dlt = g_ofLs[b*(G+1) + g];
    float dge = g_ofGs[b*(G+1) + g];

    if (g < G) {
        const int*    sidx = g_sidx + b*NN;
        const float*  E1   = g_E1   + b*NN;
        const float*  E2   = g_E2   + b*NN;
        const float2* h2   = (const float2*)g_h + (size_t)b*NN*32;
        int base = g * CH;
        #pragma unroll
        for (int j = base; j < base + CH; j++) {
            float2 hv = h2[(size_t)sidx[j]*32 + lane];
            if (j < k) {
                float e2 = E2[j];
                lt.x = fmaf(e2, hv.x, lt.x); lt.y = fmaf(e2, hv.y, lt.y);
                dlt += e2;
            } else {
                float e1 = E1[j];
                ge.x = fmaf(e1, hv.x, ge.x); ge.y = fmaf(e1, hv.y, ge.y);
                dge += e1;
            }
        }
    }

    float inv = 1.f / (cge * dge + clt * dlt);
    float o0 = (cge*ge.x + clt*lt.x) * inv;
    float o1 = (cge*ge.y + clt*lt.y) * inv;

    float2* op = (float2*)(out + (size_t)gw*64);
    op[lane] = make_float2(o0, o1);
}

// ---------------- launch ----------------
extern "C" void kernel_launch(void* const* d_in, const int* in_sizes, int n_in,
                              void* d_out, int out_size)
{
    const float* feat = (const float*)d_in[0];
    // d_in[1] = adj: unused by the reference computation — deliberately not read.
    const float* W    = (const float*)d_in[2];
    const float* a    = (const float*)d_in[3];
    float* out = (float*)d_out;

    k1_hsw<<<(BB*NN)/64, 256>>>(feat, W, a);
    k2a_sort_runs<<<BB*NRUN, 128>>>();
    k2b_rank<<<BB*NN/256, 256>>>();
    k3a_partial<<<BB*G/4, 128>>>();
    k3b_offsets<<<BB*17, 256>>>();
    k4_out<<<(BB*NN*32)/256, 256>>>(out);
}